// round 2
// baseline (speedup 1.0000x reference)
#include <cuda_runtime.h>

#define H_ 512
#define W_ 512
#define C_ 64
#define WM_ 128
#define C4_ 16                      // float4 per pixel (C=64)
#define HWC4 (H_*W_*C4_)
#define LMBDA 0.1f
#define INV_LMBDA 10.0f
#define TAU 0.1f

// ---------------- scratch (static device globals; no allocations) ----------
static __device__ float4 g_zA[2*HWC4];      // ping buffer: [comp][h][w][c4]
static __device__ float4 g_zB[2*HWC4];      // pong buffer
static __device__ float4 g_X [HWC4];        // X = U - lambda*grad_f(U)
static __device__ float4 g_P [HWC4];        // P = lambda*(Y_H@B_t + R^T@Y_M)
static __device__ float  g_T [H_*WM_*C_];   // T[h] = R @ U[h]
static __device__ float  g_M1[C_*C_];       // M1 = B @ B_t
static __device__ float  g_Rt[W_*WM_];      // R^T
static __device__ float  g_ss[4*H_];        // row sumsq partials [comp*2+chunk][h]
static __device__ float  g_scale[2];        // proj scales (s1, s2)

// ---------------- float4 helpers -------------------------------------------
__device__ __forceinline__ float4 f4add(float4 a, float4 b){ return make_float4(a.x+b.x,a.y+b.y,a.z+b.z,a.w+b.w); }
__device__ __forceinline__ float4 f4sub(float4 a, float4 b){ return make_float4(a.x-b.x,a.y-b.y,a.z-b.z,a.w-b.w); }
__device__ __forceinline__ float4 f4scl(float4 a, float s){ return make_float4(a.x*s,a.y*s,a.z*s,a.w*s); }
__device__ __forceinline__ float4 f4adds(float4 a, float s){ return make_float4(a.x+s,a.y+s,a.z+s,a.w+s); }
__device__ __forceinline__ float  f4dot(float4 a){ return a.x*a.x + a.y*a.y + a.z*a.z + a.w*a.w; }

// div components (Chambolle adjoint), on a z-component plane
__device__ __forceinline__ float4 dz1f(const float4* __restrict__ z1, int h, int w, int c4){
  if (h == 0)     return z1[w*C4_ + c4];
  if (h == H_-1)  return f4scl(z1[((H_-2)*W_ + w)*C4_ + c4], -1.f);
  return f4sub(z1[(h*W_ + w)*C4_ + c4], z1[((h-1)*W_ + w)*C4_ + c4]);
}
__device__ __forceinline__ float4 dz2f(const float4* __restrict__ z2, int h, int w, int c4){
  if (w == 0)     return z2[(h*W_)*C4_ + c4];
  if (w == W_-1)  return f4scl(z2[(h*W_ + (W_-2))*C4_ + c4], -1.f);
  return f4sub(z2[(h*W_ + w)*C4_ + c4], z2[(h*W_ + (w-1))*C4_ + c4]);
}

// ---------------- fused dual iteration -------------------------------------
// Computes w_new = (s.*w_old) + 2*TAU*gradient(div(s.*w_old) + X/LMBDA)
// and per-row sum-of-squares partials for the collaborative-norm projection.
// ONES=true: first iteration (z == ones, s == 1) -- no z loads at all.
// grid (2, H), 256 threads; blockIdx.x = w-chunk of 256 columns.
template<bool ONES>
__global__ __launch_bounds__(256)
void inner_step(const float4* __restrict__ zin, float4* __restrict__ zout,
                const float4* __restrict__ Xp, const float* __restrict__ scale,
                float* __restrict__ ss)
{
  const int h   = blockIdx.y;
  const int w0  = blockIdx.x << 8;
  const int tid = threadIdx.x;
  const float4* __restrict__ z1 = zin;
  const float4* __restrict__ z2 = zin + HWC4;
  float s1 = 1.f, s2 = 1.f;
  if (!ONES){ s1 = scale[0]; s2 = scale[1]; }
  const float tt = 2.f * TAU;
  float acc1 = 0.f, acc2 = 0.f;

#pragma unroll 1
  for (int p = 0; p < 16; ++p){
    const int flat = (p << 8) + tid;
    const int w  = w0 + (flat >> 4);
    const int c4 = flat & 15;
    const int idx = (h*W_ + w)*C4_ + c4;

    float4 d00, z1c, z2c;
    if (ONES){
      const float a = (h==0)?1.f:((h==H_-1)?-1.f:0.f);
      const float b = (w==0)?1.f:((w==W_-1)?-1.f:0.f);
      d00 = f4adds(f4scl(Xp[idx], INV_LMBDA), a + b);
      z1c = make_float4(1.f,1.f,1.f,1.f);
      z2c = z1c;
    } else {
      d00 = f4add(f4add(f4scl(dz1f(z1,h,w,c4), s1),
                        f4scl(dz2f(z2,h,w,c4), s2)),
                  f4scl(Xp[idx], INV_LMBDA));
      z1c = f4scl(z1[idx], s1);
      z2c = f4scl(z2[idx], s2);
    }

    float4 w1o = z1c, w2o = z2c;
    if (h < H_-1){
      float4 dn;
      if (ONES){
        const float a = (h+1==H_-1)?-1.f:0.f;
        const float b = (w==0)?1.f:((w==W_-1)?-1.f:0.f);
        dn = f4adds(f4scl(Xp[idx + W_*C4_], INV_LMBDA), a + b);
      } else {
        dn = f4add(f4add(f4scl(dz1f(z1,h+1,w,c4), s1),
                         f4scl(dz2f(z2,h+1,w,c4), s2)),
                   f4scl(Xp[idx + W_*C4_], INV_LMBDA));
      }
      w1o = f4add(z1c, f4scl(f4sub(dn, d00), tt));
    }
    if (w < W_-1){
      float4 de;
      if (ONES){
        const float a = (h==0)?1.f:((h==H_-1)?-1.f:0.f);
        const float b = (w+1==W_-1)?-1.f:0.f;
        de = f4adds(f4scl(Xp[idx + C4_], INV_LMBDA), a + b);
      } else {
        de = f4add(f4add(f4scl(dz1f(z1,h,w+1,c4), s1),
                         f4scl(dz2f(z2,h,w+1,c4), s2)),
                   f4scl(Xp[idx + C4_], INV_LMBDA));
      }
      w2o = f4add(z2c, f4scl(f4sub(de, d00), tt));
    }

    zout[idx]        = w1o;
    zout[HWC4 + idx] = w2o;
    acc1 += f4dot(w1o);
    acc2 += f4dot(w2o);
  }

  // deterministic block reduction (fixed tree order, fixed CTA->row ownership)
  __shared__ float sm1[256], sm2[256];
  sm1[tid] = acc1; sm2[tid] = acc2;
  __syncthreads();
  for (int s = 128; s > 0; s >>= 1){
    if (tid < s){ sm1[tid] += sm1[tid+s]; sm2[tid] += sm2[tid+s]; }
    __syncthreads();
  }
  if (tid == 0){
    ss[(0*2 + blockIdx.x)*H_ + h] = sm1[0];
    ss[(1*2 + blockIdx.x)*H_ + h] = sm2[0];
  }
}

// proj scale: norm_k = sum_h sqrt(row_sumsq), scale_k = norm>1 ? 1/norm : 1
__global__ void scale_k(const float* __restrict__ ss, float* __restrict__ scale)
{
  __shared__ float sm[256];
  const int tid = threadIdx.x;
  for (int k = 0; k < 2; ++k){
    float v = 0.f;
    for (int h = tid; h < H_; h += 256)
      v += sqrtf(ss[(2*k)*H_ + h] + ss[(2*k+1)*H_ + h]);
    sm[tid] = v;
    __syncthreads();
    for (int s = 128; s > 0; s >>= 1){
      if (tid < s) sm[tid] += sm[tid+s];
      __syncthreads();
    }
    if (tid == 0){ const float n = sm[0]; scale[k] = (n > 1.f) ? (1.f/n) : 1.f; }
    __syncthreads();
  }
}

// proxg output: U = X + LMBDA * div(s .* w)
__global__ __launch_bounds__(256)
void final_div(const float4* __restrict__ zin, const float4* __restrict__ Xp,
               const float* __restrict__ scale, float4* __restrict__ U)
{
  const int h   = blockIdx.y;
  const int w0  = blockIdx.x << 8;
  const int tid = threadIdx.x;
  const float4* __restrict__ z1 = zin;
  const float4* __restrict__ z2 = zin + HWC4;
  const float s1 = scale[0], s2 = scale[1];
#pragma unroll 1
  for (int p = 0; p < 16; ++p){
    const int flat = (p << 8) + tid;
    const int w  = w0 + (flat >> 4);
    const int c4 = flat & 15;
    const int idx = (h*W_ + w)*C4_ + c4;
    float4 dv = f4add(f4scl(dz1f(z1,h,w,c4), s1), f4scl(dz2f(z2,h,w,c4), s2));
    U[idx] = f4add(Xp[idx], f4scl(dv, LMBDA));
  }
}

// ---------------- GEMMs (fp32 SIMT, smem tiled; FLAT 256-thread blocks) -----
// T[h] = R @ U[h];  R:(128,512), U[h]:(512,64). One CTA per h, 256 threads.
__global__ __launch_bounds__(256)
void gemm_RU(float* __restrict__ T, const float* __restrict__ R, const float* __restrict__ U)
{
  const int h = blockIdx.x;
  const float* __restrict__ Uh = U + (size_t)h*W_*C_;
  __shared__ float As[32][129];   // As[k][m] = R[m][k0+k]
  __shared__ float Bs[32][64];    // Bs[k][n] = U[h][k0+k][n]
  const int tid = threadIdx.x;    // flat [0,256)
  const int tx = tid & 15, ty = tid >> 4;
  float acc[8][4] = {};
  for (int k0 = 0; k0 < 512; k0 += 32){
    for (int i = tid; i < 128*32; i += 256){
      const int m = i >> 5, k = i & 31;
      As[k][m] = R[m*512 + k0 + k];
    }
    for (int i = tid; i < 32*64; i += 256){
      const int k = i >> 6, n = i & 63;
      Bs[k][n] = Uh[(k0 + k)*64 + n];
    }
    __syncthreads();
#pragma unroll
    for (int kk = 0; kk < 32; ++kk){
      float a[8], b[4];
#pragma unroll
      for (int i = 0; i < 8; ++i) a[i] = As[kk][ty + 16*i];
#pragma unroll
      for (int j = 0; j < 4; ++j) b[j] = Bs[kk][tx + 16*j];
#pragma unroll
      for (int i = 0; i < 8; ++i)
#pragma unroll
        for (int j = 0; j < 4; ++j)
          acc[i][j] += a[i]*b[j];
    }
    __syncthreads();
  }
  float* Th = T + (size_t)h*WM_*C_;
#pragma unroll
  for (int i = 0; i < 8; ++i)
#pragma unroll
    for (int j = 0; j < 4; ++j)
      Th[(ty + 16*i)*64 + tx + 16*j] = acc[i][j];
}

// out[h] = cU*Uin[h] + cMM*(Uin[h]@M1 + Gt@Tb[h]) + cP*Pb[h]
// Gt:(512,128). grid (4, H): 128 w-rows per CTA, 256 threads.
__global__ __launch_bounds__(256)
void fused_x(float* __restrict__ out, const float* __restrict__ Uin,
             const float* __restrict__ M1, const float* __restrict__ Gt,
             const float* __restrict__ Tb, const float* __restrict__ Pb,
             float cU, float cMM, float cP)
{
  const int h  = blockIdx.y;
  const int m0 = blockIdx.x << 7;
  const float* __restrict__ Uh = Uin + (size_t)h*W_*C_;
  const float* __restrict__ Th = Tb  + (size_t)h*WM_*C_;
  __shared__ float As[32][129];
  __shared__ float Bs[32][64];
  const int tid = threadIdx.x;    // flat [0,256)
  const int tx = tid & 15, ty = tid >> 4;
  float acc[8][4] = {};

  // phase 1: Uin[h] @ M1  (K = 64)
  for (int k0 = 0; k0 < 64; k0 += 32){
    for (int i = tid; i < 128*32; i += 256){
      const int m = i >> 5, k = i & 31;
      As[k][m] = Uh[(m0 + m)*64 + k0 + k];
    }
    for (int i = tid; i < 32*64; i += 256){
      const int k = i >> 6, n = i & 63;
      Bs[k][n] = M1[(k0 + k)*64 + n];
    }
    __syncthreads();
#pragma unroll
    for (int kk = 0; kk < 32; ++kk){
      float a[8], b[4];
#pragma unroll
      for (int i = 0; i < 8; ++i) a[i] = As[kk][ty + 16*i];
#pragma unroll
      for (int j = 0; j < 4; ++j) b[j] = Bs[kk][tx + 16*j];
#pragma unroll
      for (int i = 0; i < 8; ++i)
#pragma unroll
        for (int j = 0; j < 4; ++j)
          acc[i][j] += a[i]*b[j];
    }
    __syncthreads();
  }
  // phase 2: Gt @ Tb[h]  (K = 128)
  for (int k0 = 0; k0 < 128; k0 += 32){
    for (int i = tid; i < 128*32; i += 256){
      const int m = i >> 5, k = i & 31;
      As[k][m] = Gt[(m0 + m)*128 + k0 + k];
    }
    for (int i = tid; i < 32*64; i += 256){
      const int k = i >> 6, n = i & 63;
      Bs[k][n] = Th[(k0 + k)*64 + n];
    }
    __syncthreads();
#pragma unroll
    for (int kk = 0; kk < 32; ++kk){
      float a[8], b[4];
#pragma unroll
      for (int i = 0; i < 8; ++i) a[i] = As[kk][ty + 16*i];
#pragma unroll
      for (int j = 0; j < 4; ++j) b[j] = Bs[kk][tx + 16*j];
#pragma unroll
      for (int i = 0; i < 8; ++i)
#pragma unroll
        for (int j = 0; j < 4; ++j)
          acc[i][j] += a[i]*b[j];
    }
    __syncthreads();
  }
  // epilogue
  float* Oh = out + (size_t)h*W_*C_;
  const float* Ph = Pb + (size_t)h*W_*C_;
#pragma unroll
  for (int i = 0; i < 8; ++i){
#pragma unroll
    for (int j = 0; j < 4; ++j){
      const int m = m0 + ty + 16*i;
      const int n = tx + 16*j;
      float v = cMM * acc[i][j];
      if (cU != 0.f) v += cU * Uh[m*64 + n];
      if (cP != 0.f) v += cP * Ph[m*64 + n];
      Oh[m*64 + n] = v;
    }
  }
}

__global__ void transpose_R(float* __restrict__ Rt, const float* __restrict__ R)
{
  const int i = blockIdx.x*256 + threadIdx.x;
  if (i < W_*WM_){
    const int w = i / WM_, m = i % WM_;
    Rt[i] = R[m*W_ + w];
  }
}

__global__ void compute_M1(float* __restrict__ M1, const float* __restrict__ B,
                           const float* __restrict__ Bt)
{
  const int i = blockIdx.x*256 + threadIdx.x;
  if (i < C_*C_){
    const int m = i >> 6, n = i & 63;
    float s = 0.f;
#pragma unroll 8
    for (int k = 0; k < C_; ++k) s += B[m*C_ + k]*Bt[k*C_ + n];
    M1[i] = s;
  }
}

// ---------------- driver ----------------------------------------------------
extern "C" void kernel_launch(void* const* d_in, const int* in_sizes, int n_in,
                              void* d_out, int out_size)
{
  const float* Y_H = (const float*)d_in[0];
  const float* Y_M = (const float*)d_in[1];
  const float* B   = (const float*)d_in[2];
  const float* B_t = (const float*)d_in[3];
  const float* R   = (const float*)d_in[4];
  float* U = (float*)d_out;                        // U lives in d_out

  float4 *zA, *zB, *X, *P;
  float *T, *M1, *Rt, *ss, *sc;
  cudaGetSymbolAddress((void**)&zA, g_zA);
  cudaGetSymbolAddress((void**)&zB, g_zB);
  cudaGetSymbolAddress((void**)&X,  g_X);
  cudaGetSymbolAddress((void**)&P,  g_P);
  cudaGetSymbolAddress((void**)&T,  g_T);
  cudaGetSymbolAddress((void**)&M1, g_M1);
  cudaGetSymbolAddress((void**)&Rt, g_Rt);
  cudaGetSymbolAddress((void**)&ss, g_ss);
  cudaGetSymbolAddress((void**)&sc, g_scale);

  const dim3 blk2(256);
  const dim3 grd2(2, H_);
  const dim3 blkG(256);          // FLAT 256 threads (kernels index threadIdx.x)

  // one-time precompute (per launch; deterministic)
  transpose_R<<<(W_*WM_ + 255)/256, 256>>>(Rt, R);
  compute_M1 <<<(C_*C_ + 255)/256, 256>>>(M1, B, B_t);
  // P = LMBDA*(Y_H@B_t + Rt@Y_M)   (cU=0, cP=0; Pb unused -> pass valid ptr)
  fused_x<<<dim3(4, H_), blkG>>>((float*)P, Y_H, B_t, Rt, Y_M, (const float*)X,
                                 0.f, LMBDA, 0.f);

  float4* zbuf[2] = { zA, zB };
  for (int it = 0; it < 5; ++it){
    const float4* Xp;
    if (it == 0){
      Xp = P;                                   // U = 0 -> X = P exactly
    } else {
      gemm_RU<<<H_, blkG>>>(T, R, U);
      fused_x<<<dim3(4, H_), blkG>>>((float*)X, U, M1, Rt, T, (const float*)P,
                                     1.f, -LMBDA, 1.f);
      Xp = X;
    }
    // 5 dual iterations (deferred-scale representation)
    inner_step<true><<<grd2, blk2>>>(zbuf[1], zbuf[0], Xp, sc, ss);
    scale_k<<<1, 256>>>(ss, sc);
    for (int j = 1; j < 5; ++j){
      inner_step<false><<<grd2, blk2>>>(zbuf[(j-1)&1], zbuf[j&1], Xp, sc, ss);
      scale_k<<<1, 256>>>(ss, sc);
    }
    // U = X + LMBDA*div(s .* w)   (last zout is zbuf[0])
    final_div<<<grd2, blk2>>>(zbuf[0], Xp, sc, (float4*)U);
  }
}

// round 3
// speedup vs baseline: 1.0482x; 1.0482x over previous
#include <cuda_runtime.h>

#define H_ 512
#define W_ 512
#define C_ 64
#define WM_ 128
#define C4_ 16                      // float4 per pixel (C=64)
#define HWC4 (H_*W_*C4_)
#define LMBDA 0.1f
#define INV_LMBDA 10.0f
#define TAU 0.1f

// ---------------- scratch (static device globals; no allocations) ----------
static __device__ float4 g_zA[2*HWC4];      // ping buffer: [comp][h][w][c4]
static __device__ float4 g_zB[2*HWC4];      // pong buffer
static __device__ float4 g_X [HWC4];        // X = U - lambda*grad_f(U)
static __device__ float4 g_P [HWC4];        // P = lambda*(Y_H@B_t + R^T@Y_M)
static __device__ float  g_T [H_*WM_*C_];   // T[h] = R @ U[h]
static __device__ float  g_M1[C_*C_];       // M1 = B @ B_t
static __device__ float  g_Rt[W_*WM_];      // R^T
static __device__ float  g_ssA[4*H_];       // row sumsq partials (ping)
static __device__ float  g_ssB[4*H_];       // row sumsq partials (pong)

// ---------------- float4 helpers -------------------------------------------
__device__ __forceinline__ float4 f4add(float4 a, float4 b){ return make_float4(a.x+b.x,a.y+b.y,a.z+b.z,a.w+b.w); }
__device__ __forceinline__ float4 f4sub(float4 a, float4 b){ return make_float4(a.x-b.x,a.y-b.y,a.z-b.z,a.w-b.w); }
__device__ __forceinline__ float4 f4scl(float4 a, float s){ return make_float4(a.x*s,a.y*s,a.z*s,a.w*s); }
__device__ __forceinline__ float4 f4adds(float4 a, float s){ return make_float4(a.x+s,a.y+s,a.z+s,a.w+s); }
__device__ __forceinline__ float  f4dot(float4 a){ return a.x*a.x + a.y*a.y + a.z*a.z + a.w*a.w; }

// ---------------- packed f32x2 helpers (Blackwell packed fp32 pipe) --------
__device__ __forceinline__ unsigned long long pk2(float lo, float hi){
  unsigned long long r;
  asm("mov.b64 %0, {%1, %2};" : "=l"(r)
      : "r"(__float_as_uint(lo)), "r"(__float_as_uint(hi)));
  return r;
}
__device__ __forceinline__ void upk2(unsigned long long v, float& lo, float& hi){
  unsigned int a, b;
  asm("mov.b64 {%0, %1}, %2;" : "=r"(a), "=r"(b) : "l"(v));
  lo = __uint_as_float(a); hi = __uint_as_float(b);
}
#define FMA2(d,a,b) asm("fma.rn.f32x2 %0, %1, %2, %0;" : "+l"(d) : "l"(a), "l"(b))

// ---------------- div components (Chambolle adjoint) ------------------------
__device__ __forceinline__ float4 dz1f(const float4* __restrict__ z1, int h, int w, int c4){
  if (h == 0)     return z1[w*C4_ + c4];
  if (h == H_-1)  return f4scl(z1[((H_-2)*W_ + w)*C4_ + c4], -1.f);
  return f4sub(z1[(h*W_ + w)*C4_ + c4], z1[((h-1)*W_ + w)*C4_ + c4]);
}
__device__ __forceinline__ float4 dz2f(const float4* __restrict__ z2, int h, int w, int c4){
  if (w == 0)     return z2[(h*W_)*C4_ + c4];
  if (w == W_-1)  return f4scl(z2[(h*W_ + (W_-2))*C4_ + c4], -1.f);
  return f4sub(z2[(h*W_ + w)*C4_ + c4], z2[(h*W_ + (w-1))*C4_ + c4]);
}

// ---------------- inline projection scale (replaces scale_k kernel) ---------
// Every CTA computes the two scales identically (fixed order -> deterministic).
__device__ __forceinline__ void get_scales(const float* __restrict__ ss,
                                           float& s1, float& s2){
  __shared__ float gs1[256], gs2[256];
  const int tid = threadIdx.x;
  float v1 = 0.f, v2 = 0.f;
  for (int h = tid; h < H_; h += 256){
    v1 += sqrtf(ss[h]       + ss[H_   + h]);
    v2 += sqrtf(ss[2*H_ + h] + ss[3*H_ + h]);
  }
  gs1[tid] = v1; gs2[tid] = v2;
  __syncthreads();
  for (int s = 128; s > 0; s >>= 1){
    if (tid < s){ gs1[tid] += gs1[tid+s]; gs2[tid] += gs2[tid+s]; }
    __syncthreads();
  }
  const float n1 = gs1[0], n2 = gs2[0];
  s1 = (n1 > 1.f) ? (1.f/n1) : 1.f;
  s2 = (n2 > 1.f) ? (1.f/n2) : 1.f;
  __syncthreads();
}

// ---------------- fused dual iteration -------------------------------------
// w_new = (s.*w_old) + 2*TAU*gradient(div(s.*w_old) + X/LMBDA)
// + per-row sum-of-squares partials for the projection.
// ONES=true: first inner iteration (z == ones, s == 1): no z/ss loads.
template<bool ONES>
__global__ __launch_bounds__(256)
void inner_step(const float4* __restrict__ zin, float4* __restrict__ zout,
                const float4* __restrict__ Xp, const float* __restrict__ ssin,
                float* __restrict__ ssout)
{
  const int h   = blockIdx.y;
  const int w0  = blockIdx.x << 8;
  const int tid = threadIdx.x;
  const float4* __restrict__ z1 = zin;
  const float4* __restrict__ z2 = zin + HWC4;
  float s1 = 1.f, s2 = 1.f;
  if (!ONES) get_scales(ssin, s1, s2);
  const float tt = 2.f * TAU;
  float acc1 = 0.f, acc2 = 0.f;

#pragma unroll 1
  for (int p = 0; p < 16; ++p){
    const int flat = (p << 8) + tid;
    const int w  = w0 + (flat >> 4);
    const int c4 = flat & 15;
    const int idx = (h*W_ + w)*C4_ + c4;

    float4 d00, z1c, z2c;
    if (ONES){
      const float a = (h==0)?1.f:((h==H_-1)?-1.f:0.f);
      const float b = (w==0)?1.f:((w==W_-1)?-1.f:0.f);
      d00 = f4adds(f4scl(Xp[idx], INV_LMBDA), a + b);
      z1c = make_float4(1.f,1.f,1.f,1.f);
      z2c = z1c;
    } else {
      d00 = f4add(f4add(f4scl(dz1f(z1,h,w,c4), s1),
                        f4scl(dz2f(z2,h,w,c4), s2)),
                  f4scl(Xp[idx], INV_LMBDA));
      z1c = f4scl(z1[idx], s1);
      z2c = f4scl(z2[idx], s2);
    }

    float4 w1o = z1c, w2o = z2c;
    if (h < H_-1){
      float4 dn;
      if (ONES){
        const float a = (h+1==H_-1)?-1.f:0.f;
        const float b = (w==0)?1.f:((w==W_-1)?-1.f:0.f);
        dn = f4adds(f4scl(Xp[idx + W_*C4_], INV_LMBDA), a + b);
      } else {
        dn = f4add(f4add(f4scl(dz1f(z1,h+1,w,c4), s1),
                         f4scl(dz2f(z2,h+1,w,c4), s2)),
                   f4scl(Xp[idx + W_*C4_], INV_LMBDA));
      }
      w1o = f4add(z1c, f4scl(f4sub(dn, d00), tt));
    }
    if (w < W_-1){
      float4 de;
      if (ONES){
        const float a = (h==0)?1.f:((h==H_-1)?-1.f:0.f);
        const float b = (w+1==W_-1)?-1.f:0.f;
        de = f4adds(f4scl(Xp[idx + C4_], INV_LMBDA), a + b);
      } else {
        de = f4add(f4add(f4scl(dz1f(z1,h,w+1,c4), s1),
                         f4scl(dz2f(z2,h,w+1,c4), s2)),
                   f4scl(Xp[idx + C4_], INV_LMBDA));
      }
      w2o = f4add(z2c, f4scl(f4sub(de, d00), tt));
    }

    zout[idx]        = w1o;
    zout[HWC4 + idx] = w2o;
    acc1 += f4dot(w1o);
    acc2 += f4dot(w2o);
  }

  __shared__ float sm1[256], sm2[256];
  sm1[tid] = acc1; sm2[tid] = acc2;
  __syncthreads();
  for (int s = 128; s > 0; s >>= 1){
    if (tid < s){ sm1[tid] += sm1[tid+s]; sm2[tid] += sm2[tid+s]; }
    __syncthreads();
  }
  if (tid == 0){
    ssout[(0*2 + blockIdx.x)*H_ + h] = sm1[0];
    ssout[(1*2 + blockIdx.x)*H_ + h] = sm2[0];
  }
}

// proxg output: U = X + LMBDA * div(s .* w)
__global__ __launch_bounds__(256)
void final_div(const float4* __restrict__ zin, const float4* __restrict__ Xp,
               const float* __restrict__ ssin, float4* __restrict__ U)
{
  const int h   = blockIdx.y;
  const int w0  = blockIdx.x << 8;
  const int tid = threadIdx.x;
  const float4* __restrict__ z1 = zin;
  const float4* __restrict__ z2 = zin + HWC4;
  float s1, s2;
  get_scales(ssin, s1, s2);
#pragma unroll 1
  for (int p = 0; p < 16; ++p){
    const int flat = (p << 8) + tid;
    const int w  = w0 + (flat >> 4);
    const int c4 = flat & 15;
    const int idx = (h*W_ + w)*C4_ + c4;
    float4 dv = f4add(f4scl(dz1f(z1,h,w,c4), s1), f4scl(dz2f(z2,h,w,c4), s2));
    U[idx] = f4add(Xp[idx], f4scl(dv, LMBDA));
  }
}

// ---------------- f32x2 GEMM worker -----------------------------------------
// C(128x64) += A(128xK) @ B(Kx64). 128 threads; 8x8 per-thread tile;
// packed fp32 FMA (2 exact RN FMAs per instruction).
// As: [k][m] stride 132; Bs: [k][n] stride 68.
__device__ __forceinline__ void mm_tiles(const float* __restrict__ A, int lda,
                                         const float* __restrict__ Bg, int ldb,
                                         int K, unsigned long long (&acc)[8][4],
                                         float* As, float* Bs)
{
  const int tid = threadIdx.x;
  const int tx = tid & 7;     // n-group: n0 = tx*8
  const int ty = tid >> 3;    // m-group: m = ty*8 + i
  for (int k0 = 0; k0 < K; k0 += 32){
    // fill As (transpose: one m-row per thread; conflict-free scalar stores)
    {
      const float* Ar = A + (size_t)tid*lda + k0;
#pragma unroll
      for (int q = 0; q < 8; ++q){
        const float4 v = *(const float4*)(Ar + 4*q);
        As[(4*q+0)*132 + tid] = v.x;
        As[(4*q+1)*132 + tid] = v.y;
        As[(4*q+2)*132 + tid] = v.z;
        As[(4*q+3)*132 + tid] = v.w;
      }
    }
    // fill Bs (row-major, float4)
    {
      const int n4 = tid & 15, kb = tid >> 4;   // kb 0..7
#pragma unroll
      for (int t = 0; t < 4; ++t){
        const int k = kb + 8*t;
        *(float4*)(Bs + k*68 + 4*n4) =
          *(const float4*)(Bg + (size_t)(k0+k)*ldb + 4*n4);
      }
    }
    __syncthreads();
#pragma unroll 8
    for (int kk = 0; kk < 32; ++kk){
      const float4 a0 = *(const float4*)(As + kk*132 + ty*8);
      const float4 a1 = *(const float4*)(As + kk*132 + ty*8 + 4);
      const float4 b0 = *(const float4*)(Bs + kk*68 + tx*8);
      const float4 b1 = *(const float4*)(Bs + kk*68 + tx*8 + 4);
      unsigned long long pb[4];
      pb[0] = pk2(b0.x, b0.y); pb[1] = pk2(b0.z, b0.w);
      pb[2] = pk2(b1.x, b1.y); pb[3] = pk2(b1.z, b1.w);
      const float av[8] = {a0.x,a0.y,a0.z,a0.w,a1.x,a1.y,a1.z,a1.w};
#pragma unroll
      for (int i = 0; i < 8; ++i){
        const unsigned long long pa = pk2(av[i], av[i]);
#pragma unroll
        for (int j = 0; j < 4; ++j) FMA2(acc[i][j], pa, pb[j]);
      }
    }
    __syncthreads();
  }
}

// T[h] = R @ U[h];  R:(128,512), U[h]:(512,64). One CTA per h.
__global__ __launch_bounds__(128)
void gemm_RU(float* __restrict__ T, const float* __restrict__ R,
             const float* __restrict__ U)
{
  __shared__ float As[32*132];
  __shared__ float Bs[32*68];
  const int h = blockIdx.x;
  unsigned long long acc[8][4];
#pragma unroll
  for (int i = 0; i < 8; ++i)
#pragma unroll
    for (int j = 0; j < 4; ++j) acc[i][j] = 0ULL;

  mm_tiles(R, 512, U + (size_t)h*W_*C_, 64, 512, acc, As, Bs);

  const int tx = threadIdx.x & 7, ty = threadIdx.x >> 3;
  float* Th = T + (size_t)h*WM_*C_;
#pragma unroll
  for (int i = 0; i < 8; ++i){
    float o[8];
#pragma unroll
    for (int j = 0; j < 4; ++j) upk2(acc[i][j], o[2*j], o[2*j+1]);
    const int r = ty*8 + i;
    *(float4*)(Th + (size_t)r*64 + tx*8)     = make_float4(o[0],o[1],o[2],o[3]);
    *(float4*)(Th + (size_t)r*64 + tx*8 + 4) = make_float4(o[4],o[5],o[6],o[7]);
  }
}

// out[h] = cU*Uin[h] + cMM*(Uin[h]@M1 + Gt@Tb[h]) + cP*Pb[h]
// Gt:(512,128). grid (4, H): 128 W-rows per CTA.
__global__ __launch_bounds__(128)
void fused_x(float* __restrict__ out, const float* __restrict__ Uin,
             const float* __restrict__ M1, const float* __restrict__ Gt,
             const float* __restrict__ Tb, const float* __restrict__ Pb,
             float cU, float cMM, float cP)
{
  __shared__ float As[32*132];
  __shared__ float Bs[32*68];
  const int h  = blockIdx.y;
  const int m0 = blockIdx.x << 7;
  const float* __restrict__ Uh = Uin + (size_t)h*W_*C_;
  unsigned long long acc[8][4];
#pragma unroll
  for (int i = 0; i < 8; ++i)
#pragma unroll
    for (int j = 0; j < 4; ++j) acc[i][j] = 0ULL;

  // phase 1: Uin[h][m0:m0+128] @ M1  (K = 64)
  mm_tiles(Uh + (size_t)m0*C_, C_, M1, C_, C_, acc, As, Bs);
  // phase 2: Gt[m0:m0+128] @ Tb[h]   (K = 128)
  mm_tiles(Gt + (size_t)m0*WM_, WM_, Tb + (size_t)h*WM_*C_, C_, WM_, acc, As, Bs);

  const int tx = threadIdx.x & 7, ty = threadIdx.x >> 3;
  float* Oh = out + (size_t)h*W_*C_;
  const float* Ph = Pb + (size_t)h*W_*C_;
#pragma unroll
  for (int i = 0; i < 8; ++i){
    float o[8];
#pragma unroll
    for (int j = 0; j < 4; ++j) upk2(acc[i][j], o[2*j], o[2*j+1]);
    const int r = m0 + ty*8 + i;
    float res[8];
#pragma unroll
    for (int q = 0; q < 8; ++q) res[q] = cMM * o[q];
    if (cU != 0.f){
      const float4 u0 = *(const float4*)(Uh + (size_t)r*64 + tx*8);
      const float4 u1 = *(const float4*)(Uh + (size_t)r*64 + tx*8 + 4);
      res[0]+=cU*u0.x; res[1]+=cU*u0.y; res[2]+=cU*u0.z; res[3]+=cU*u0.w;
      res[4]+=cU*u1.x; res[5]+=cU*u1.y; res[6]+=cU*u1.z; res[7]+=cU*u1.w;
    }
    if (cP != 0.f){
      const float4 p0 = *(const float4*)(Ph + (size_t)r*64 + tx*8);
      const float4 p1 = *(const float4*)(Ph + (size_t)r*64 + tx*8 + 4);
      res[0]+=cP*p0.x; res[1]+=cP*p0.y; res[2]+=cP*p0.z; res[3]+=cP*p0.w;
      res[4]+=cP*p1.x; res[5]+=cP*p1.y; res[6]+=cP*p1.z; res[7]+=cP*p1.w;
    }
    *(float4*)(Oh + (size_t)r*64 + tx*8)     = make_float4(res[0],res[1],res[2],res[3]);
    *(float4*)(Oh + (size_t)r*64 + tx*8 + 4) = make_float4(res[4],res[5],res[6],res[7]);
  }
}

__global__ void transpose_R(float* __restrict__ Rt, const float* __restrict__ R)
{
  const int i = blockIdx.x*256 + threadIdx.x;
  if (i < W_*WM_){
    const int w = i / WM_, m = i % WM_;
    Rt[i] = R[m*W_ + w];
  }
}

__global__ void compute_M1(float* __restrict__ M1, const float* __restrict__ B,
                           const float* __restrict__ Bt)
{
  const int i = blockIdx.x*256 + threadIdx.x;
  if (i < C_*C_){
    const int m = i >> 6, n = i & 63;
    float s = 0.f;
#pragma unroll 8
    for (int k = 0; k < C_; ++k) s += B[m*C_ + k]*Bt[k*C_ + n];
    M1[i] = s;
  }
}

// ---------------- driver ----------------------------------------------------
extern "C" void kernel_launch(void* const* d_in, const int* in_sizes, int n_in,
                              void* d_out, int out_size)
{
  const float* Y_H = (const float*)d_in[0];
  const float* Y_M = (const float*)d_in[1];
  const float* B   = (const float*)d_in[2];
  const float* B_t = (const float*)d_in[3];
  const float* R   = (const float*)d_in[4];
  float* U = (float*)d_out;                        // U lives in d_out

  float4 *zA, *zB, *X, *P;
  float *T, *M1, *Rt, *ssA, *ssB;
  cudaGetSymbolAddress((void**)&zA,  g_zA);
  cudaGetSymbolAddress((void**)&zB,  g_zB);
  cudaGetSymbolAddress((void**)&X,   g_X);
  cudaGetSymbolAddress((void**)&P,   g_P);
  cudaGetSymbolAddress((void**)&T,   g_T);
  cudaGetSymbolAddress((void**)&M1,  g_M1);
  cudaGetSymbolAddress((void**)&Rt,  g_Rt);
  cudaGetSymbolAddress((void**)&ssA, g_ssA);
  cudaGetSymbolAddress((void**)&ssB, g_ssB);

  const dim3 blk2(256);
  const dim3 grd2(2, H_);
  const dim3 blkG(128);

  // one-time precompute (per launch; deterministic)
  transpose_R<<<(W_*WM_ + 255)/256, 256>>>(Rt, R);
  compute_M1 <<<(C_*C_ + 255)/256, 256>>>(M1, B, B_t);
  // P = LMBDA*(Y_H@B_t + Rt@Y_M)   (cU=0, cP=0)
  fused_x<<<dim3(4, H_), blkG>>>((float*)P, Y_H, B_t, Rt, Y_M, (const float*)X,
                                 0.f, LMBDA, 0.f);

  float4* zbuf[2]  = { zA, zB };
  float*  ssbuf[2] = { ssA, ssB };
  for (int it = 0; it < 5; ++it){
    const float4* Xp;
    if (it == 0){
      Xp = P;                                   // U = 0 -> X = P exactly
    } else {
      gemm_RU<<<H_, blkG>>>(T, R, U);
      fused_x<<<dim3(4, H_), blkG>>>((float*)X, U, M1, Rt, T, (const float*)P,
                                     1.f, -LMBDA, 1.f);
      Xp = X;
    }
    // 5 dual iterations; scales computed inline from double-buffered ss
    inner_step<true><<<grd2, blk2>>>(zbuf[1], zbuf[0], Xp, ssbuf[1], ssbuf[0]);
    for (int j = 1; j < 5; ++j){
      inner_step<false><<<grd2, blk2>>>(zbuf[(j-1)&1], zbuf[j&1], Xp,
                                        ssbuf[(j-1)&1], ssbuf[j&1]);
    }
    // last inner step j=4 wrote zbuf[0], ssbuf[0]
    final_div<<<grd2, blk2>>>(zbuf[0], Xp, ssbuf[0], (float4*)U);
  }
}

// round 6
// speedup vs baseline: 1.0865x; 1.0365x over previous
#include <cuda_runtime.h>
#include <cuda_fp16.h>

#define H_ 512
#define W_ 512
#define C_ 64
#define WM_ 128
#define G8_ 8                       // half8 groups per pixel (C=64 -> 8 groups)
#define C4_ 16                      // float4 per pixel
#define HWG (H_*W_*G8_)             // uint4 elements per z component plane
#define HWC4 (H_*W_*C4_)
#define LMBDA 0.1f
#define INV_LMBDA 10.0f
#define TAU 0.1f

// ---------------- scratch (static device globals; no allocations) ----------
static __device__ uint4  g_zA[2*HWG];       // z ping (half storage): [comp][h][w][g]
static __device__ uint4  g_zB[2*HWG];       // z pong
static __device__ float4 g_X [HWC4];        // X = U - lambda*grad_f(U)
static __device__ float4 g_P [HWC4];        // P = lambda*(Y_H@B_t + R^T@Y_M)
static __device__ float  g_T [H_*WM_*C_];   // T[h] = R @ U[h]
static __device__ float  g_M1[C_*C_];       // M1 = B @ B_t
static __device__ float  g_Rt[W_*WM_];      // R^T
static __device__ float  g_ssA[2*H_];       // row sumsq (ping)  [comp][h]
static __device__ float  g_ssB[2*H_];       // row sumsq (pong)

// ---------------- F8: 8 fp32 lanes <-> half8 in one uint4 -------------------
struct F8 { float a[8]; };

__device__ __forceinline__ F8 ldz8(const uint4* __restrict__ z, int idx){
  uint4 v = z[idx];
  unsigned u[4] = {v.x, v.y, v.z, v.w};
  F8 r;
#pragma unroll
  for (int i = 0; i < 4; ++i){
    float2 f = __half22float2(*reinterpret_cast<__half2*>(&u[i]));
    r.a[2*i] = f.x; r.a[2*i+1] = f.y;
  }
  return r;
}
__device__ __forceinline__ void stz8(uint4* __restrict__ z, int idx, const F8& r){
  unsigned u[4];
#pragma unroll
  for (int i = 0; i < 4; ++i){
    __half2 h = __floats2half2_rn(r.a[2*i], r.a[2*i+1]);
    u[i] = *reinterpret_cast<unsigned*>(&h);
  }
  z[idx] = make_uint4(u[0], u[1], u[2], u[3]);
}
__device__ __forceinline__ F8 f8sub(F8 x, F8 y){ F8 r;
#pragma unroll
  for (int i=0;i<8;++i) r.a[i]=x.a[i]-y.a[i]; return r; }
__device__ __forceinline__ F8 f8neg(F8 x){ F8 r;
#pragma unroll
  for (int i=0;i<8;++i) r.a[i]=-x.a[i]; return r; }
__device__ __forceinline__ float f8dot(const F8& x){ float s=0.f;
#pragma unroll
  for (int i=0;i<8;++i) s += x.a[i]*x.a[i]; return s; }

// load 8 fp32 (two float4) from X at pixel (h,w), group g
__device__ __forceinline__ F8 ldx8(const float4* __restrict__ X, int h, int w, int g){
  const int i4 = (h*W_ + w)*C4_ + 2*g;
  const float4 p = X[i4], q = X[i4+1];
  F8 r; r.a[0]=p.x; r.a[1]=p.y; r.a[2]=p.z; r.a[3]=p.w;
        r.a[4]=q.x; r.a[5]=q.y; r.a[6]=q.z; r.a[7]=q.w;
  return r;
}

// dz components (Chambolle adjoint) on half z planes, scale applied by caller
__device__ __forceinline__ F8 dz1h(const uint4* __restrict__ z1, int h, int w, int g){
  if (h == 0)     return ldz8(z1, (0*W_ + w)*G8_ + g);
  if (h == H_-1)  return f8neg(ldz8(z1, ((H_-2)*W_ + w)*G8_ + g));
  return f8sub(ldz8(z1, (h*W_ + w)*G8_ + g), ldz8(z1, ((h-1)*W_ + w)*G8_ + g));
}
__device__ __forceinline__ F8 dz2h(const uint4* __restrict__ z2, int h, int w, int g){
  if (w == 0)     return ldz8(z2, (h*W_)*G8_ + g);
  if (w == W_-1)  return f8neg(ldz8(z2, (h*W_ + (W_-2))*G8_ + g));
  return f8sub(ldz8(z2, (h*W_ + w)*G8_ + g), ldz8(z2, (h*W_ + (w-1))*G8_ + g));
}

// d = s1*dz1 + s2*dz2 + X/lambda at (h,w,g)
__device__ __forceinline__ F8 dcalc(const uint4* __restrict__ z1,
                                    const uint4* __restrict__ z2,
                                    const float4* __restrict__ X,
                                    int h, int w, int g, float s1, float s2){
  const F8 a = dz1h(z1, h, w, g);
  const F8 b = dz2h(z2, h, w, g);
  const F8 x = ldx8(X, h, w, g);
  F8 d;
#pragma unroll
  for (int i = 0; i < 8; ++i) d.a[i] = fmaf(s1, a.a[i], fmaf(s2, b.a[i], INV_LMBDA*x.a[i]));
  return d;
}
// ONES variant: z == 1 -> dz1 = edge const, dz2 = edge const
__device__ __forceinline__ F8 dcalc1(const float4* __restrict__ X, int h, int w, int g){
  const float a = (h==0)?1.f:((h==H_-1)?-1.f:0.f);
  const float b = (w==0)?1.f:((w==W_-1)?-1.f:0.f);
  const F8 x = ldx8(X, h, w, g);
  F8 d;
#pragma unroll
  for (int i = 0; i < 8; ++i) d.a[i] = fmaf(INV_LMBDA, x.a[i], a + b);
  return d;
}

// ---------------- inline projection scale ----------------------------------
// Every CTA recomputes the two scales identically (fixed order -> deterministic).
__device__ __forceinline__ void get_scales(const float* __restrict__ ss,
                                           float& s1, float& s2){
  __shared__ float gs1[256], gs2[256];
  const int tid = threadIdx.x;
  float v1 = 0.f, v2 = 0.f;
  for (int h = tid; h < H_; h += 256){
    v1 += sqrtf(ss[h]);
    v2 += sqrtf(ss[H_ + h]);
  }
  gs1[tid] = v1; gs2[tid] = v2;
  __syncthreads();
  for (int s = 128; s > 0; s >>= 1){
    if (tid < s){ gs1[tid] += gs1[tid+s]; gs2[tid] += gs2[tid+s]; }
    __syncthreads();
  }
  const float n1 = gs1[0], n2 = gs2[0];
  s1 = (n1 > 1.f) ? (1.f/n1) : 1.f;
  s2 = (n2 > 1.f) ? (1.f/n2) : 1.f;
  __syncthreads();
}

// ---------------- fused dual iteration -------------------------------------
// w_new = (s.*z) + 2*TAU*gradient(div(s.*z) + X/LMBDA); ss partial per row.
// grid (H_), 256 threads; each thread handles 16 half8 groups of its row.
template<bool ONES>
__global__ __launch_bounds__(256)
void inner_step(const uint4* __restrict__ zin, uint4* __restrict__ zout,
                const float4* __restrict__ Xp, const float* __restrict__ ssin,
                float* __restrict__ ssout)
{
  const int h   = blockIdx.x;
  const int tid = threadIdx.x;
  const uint4* __restrict__ z1 = zin;
  const uint4* __restrict__ z2 = zin + HWG;
  float s1 = 1.f, s2 = 1.f;
  if (!ONES) get_scales(ssin, s1, s2);
  const float tt = 2.f * TAU;
  float acc1 = 0.f, acc2 = 0.f;

#pragma unroll 1
  for (int p = 0; p < 16; ++p){
    const int flat = (p << 8) + tid;       // 0..4095
    const int w  = flat >> 3;
    const int g  = flat & 7;
    const int idx = (h*W_ + w)*G8_ + g;

    F8 d00, z1c, z2c;
    if (ONES){
      d00 = dcalc1(Xp, h, w, g);
#pragma unroll
      for (int i = 0; i < 8; ++i){ z1c.a[i] = 1.f; z2c.a[i] = 1.f; }
    } else {
      d00 = dcalc(z1, z2, Xp, h, w, g, s1, s2);
      const F8 za = ldz8(z1, idx), zb = ldz8(z2, idx);
#pragma unroll
      for (int i = 0; i < 8; ++i){ z1c.a[i] = s1*za.a[i]; z2c.a[i] = s2*zb.a[i]; }
    }

    F8 w1o = z1c, w2o = z2c;
    if (h < H_-1){
      const F8 dn = ONES ? dcalc1(Xp, h+1, w, g)
                         : dcalc(z1, z2, Xp, h+1, w, g, s1, s2);
#pragma unroll
      for (int i = 0; i < 8; ++i) w1o.a[i] = fmaf(tt, dn.a[i]-d00.a[i], z1c.a[i]);
    }
    if (w < W_-1){
      const F8 de = ONES ? dcalc1(Xp, h, w+1, g)
                         : dcalc(z1, z2, Xp, h, w+1, g, s1, s2);
#pragma unroll
      for (int i = 0; i < 8; ++i) w2o.a[i] = fmaf(tt, de.a[i]-d00.a[i], z2c.a[i]);
    }

    stz8(zout, idx, w1o);
    stz8(zout + HWG, idx, w2o);
    acc1 += f8dot(w1o);
    acc2 += f8dot(w2o);
  }

  __shared__ float sm1[256], sm2[256];
  sm1[tid] = acc1; sm2[tid] = acc2;
  __syncthreads();
  for (int s = 128; s > 0; s >>= 1){
    if (tid < s){ sm1[tid] += sm1[tid+s]; sm2[tid] += sm2[tid+s]; }
    __syncthreads();
  }
  if (tid == 0){
    ssout[h]      = sm1[0];
    ssout[H_ + h] = sm2[0];
  }
}

// proxg output: U = X + LMBDA * div(s .* z)
__global__ __launch_bounds__(256)
void final_div(const uint4* __restrict__ zin, const float4* __restrict__ Xp,
               const float* __restrict__ ssin, float4* __restrict__ U)
{
  const int h   = blockIdx.x;
  const int tid = threadIdx.x;
  const uint4* __restrict__ z1 = zin;
  const uint4* __restrict__ z2 = zin + HWG;
  float s1, s2;
  get_scales(ssin, s1, s2);
#pragma unroll 1
  for (int p = 0; p < 16; ++p){
    const int flat = (p << 8) + tid;
    const int w  = flat >> 3;
    const int g  = flat & 7;
    const F8 a = dz1h(z1, h, w, g);
    const F8 b = dz2h(z2, h, w, g);
    const F8 x = ldx8(Xp, h, w, g);
    F8 r;
#pragma unroll
    for (int i = 0; i < 8; ++i)
      r.a[i] = fmaf(LMBDA, fmaf(s1, a.a[i], s2*b.a[i]), x.a[i]);
    const int i4 = (h*W_ + w)*C4_ + 2*g;
    U[i4]   = make_float4(r.a[0], r.a[1], r.a[2], r.a[3]);
    U[i4+1] = make_float4(r.a[4], r.a[5], r.a[6], r.a[7]);
  }
}

// ---------------- packed f32x2 helpers (Blackwell packed fp32 pipe) --------
__device__ __forceinline__ unsigned long long pk2(float lo, float hi){
  unsigned long long r;
  asm("mov.b64 %0, {%1, %2};" : "=l"(r)
      : "r"(__float_as_uint(lo)), "r"(__float_as_uint(hi)));
  return r;
}
__device__ __forceinline__ void upk2(unsigned long long v, float& lo, float& hi){
  unsigned int a, b;
  asm("mov.b64 {%0, %1}, %2;" : "=r"(a), "=r"(b) : "l"(v));
  lo = __uint_as_float(a); hi = __uint_as_float(b);
}
#define FMA2(d,a,b) asm("fma.rn.f32x2 %0, %1, %2, %0;" : "+l"(d) : "l"(a), "l"(b))

// ---------------- f32x2 GEMM worker -----------------------------------------
// C(128x64) += A(128xK) @ B(Kx64). 128 threads; 8x8 per-thread tile.
__device__ __forceinline__ void mm_tiles(const float* __restrict__ A, int lda,
                                         const float* __restrict__ Bg, int ldb,
                                         int K, unsigned long long (&acc)[8][4],
                                         float* As, float* Bs)
{
  const int tid = threadIdx.x;
  const int tx = tid & 7;
  const int ty = tid >> 3;
  for (int k0 = 0; k0 < K; k0 += 32){
    {
      const float* Ar = A + (size_t)tid*lda + k0;
#pragma unroll
      for (int q = 0; q < 8; ++q){
        const float4 v = *(const float4*)(Ar + 4*q);
        As[(4*q+0)*132 + tid] = v.x;
        As[(4*q+1)*132 + tid] = v.y;
        As[(4*q+2)*132 + tid] = v.z;
        As[(4*q+3)*132 + tid] = v.w;
      }
    }
    {
      const int n4 = tid & 15, kb = tid >> 4;
#pragma unroll
      for (int t = 0; t < 4; ++t){
        const int k = kb + 8*t;
        *(float4*)(Bs + k*68 + 4*n4) =
          *(const float4*)(Bg + (size_t)(k0+k)*ldb + 4*n4);
      }
    }
    __syncthreads();
#pragma unroll 8
    for (int kk = 0; kk < 32; ++kk){
      const float4 a0 = *(const float4*)(As + kk*132 + ty*8);
      const float4 a1 = *(const float4*)(As + kk*132 + ty*8 + 4);
      const float4 b0 = *(const float4*)(Bs + kk*68 + tx*8);
      const float4 b1 = *(const float4*)(Bs + kk*68 + tx*8 + 4);
      unsigned long long pb[4];
      pb[0] = pk2(b0.x, b0.y); pb[1] = pk2(b0.z, b0.w);
      pb[2] = pk2(b1.x, b1.y); pb[3] = pk2(b1.z, b1.w);
      const float av[8] = {a0.x,a0.y,a0.z,a0.w,a1.x,a1.y,a1.z,a1.w};
#pragma unroll
      for (int i = 0; i < 8; ++i){
        const unsigned long long pa = pk2(av[i], av[i]);
#pragma unroll
        for (int j = 0; j < 4; ++j) FMA2(acc[i][j], pa, pb[j]);
      }
    }
    __syncthreads();
  }
}

// T[h] = R @ U[h];  R:(128,512), U[h]:(512,64). One CTA per h.
__global__ __launch_bounds__(128)
void gemm_RU(float* __restrict__ T, const float* __restrict__ R,
             const float* __restrict__ U)
{
  __shared__ float As[32*132];
  __shared__ float Bs[32*68];
  const int h = blockIdx.x;
  unsigned long long acc[8][4];
#pragma unroll
  for (int i = 0; i < 8; ++i)
#pragma unroll
    for (int j = 0; j < 4; ++j) acc[i][j] = 0ULL;

  mm_tiles(R, 512, U + (size_t)h*W_*C_, 64, 512, acc, As, Bs);

  const int tx = threadIdx.x & 7, ty = threadIdx.x >> 3;
  float* Th = T + (size_t)h*WM_*C_;
#pragma unroll
  for (int i = 0; i < 8; ++i){
    float o[8];
#pragma unroll
    for (int j = 0; j < 4; ++j) upk2(acc[i][j], o[2*j], o[2*j+1]);
    const int r = ty*8 + i;
    *(float4*)(Th + (size_t)r*64 + tx*8)     = make_float4(o[0],o[1],o[2],o[3]);
    *(float4*)(Th + (size_t)r*64 + tx*8 + 4) = make_float4(o[4],o[5],o[6],o[7]);
  }
}

// out[h] = cU*Uin[h] + cMM*(Uin[h]@M1 + Gt@Tb[h]) + cP*Pb[h]
__global__ __launch_bounds__(128)
void fused_x(float* __restrict__ out, const float* __restrict__ Uin,
             const float* __restrict__ M1, const float* __restrict__ Gt,
             const float* __restrict__ Tb, const float* __restrict__ Pb,
             float cU, float cMM, float cP)
{
  __shared__ float As[32*132];
  __shared__ float Bs[32*68];
  const int h  = blockIdx.y;
  const int m0 = blockIdx.x << 7;
  const float* __restrict__ Uh = Uin + (size_t)h*W_*C_;
  unsigned long long acc[8][4];
#pragma unroll
  for (int i = 0; i < 8; ++i)
#pragma unroll
    for (int j = 0; j < 4; ++j) acc[i][j] = 0ULL;

  mm_tiles(Uh + (size_t)m0*C_, C_, M1, C_, C_, acc, As, Bs);
  mm_tiles(Gt + (size_t)m0*WM_, WM_, Tb + (size_t)h*WM_*C_, C_, WM_, acc, As, Bs);

  const int tx = threadIdx.x & 7, ty = threadIdx.x >> 3;
  float* Oh = out + (size_t)h*W_*C_;
  const float* Ph = Pb + (size_t)h*W_*C_;
#pragma unroll
  for (int i = 0; i < 8; ++i){
    float o[8];
#pragma unroll
    for (int j = 0; j < 4; ++j) upk2(acc[i][j], o[2*j], o[2*j+1]);
    const int r = m0 + ty*8 + i;
    float res[8];
#pragma unroll
    for (int q = 0; q < 8; ++q) res[q] = cMM * o[q];
    if (cU != 0.f){
      const float4 u0 = *(const float4*)(Uh + (size_t)r*64 + tx*8);
      const float4 u1 = *(const float4*)(Uh + (size_t)r*64 + tx*8 + 4);
      res[0]+=cU*u0.x; res[1]+=cU*u0.y; res[2]+=cU*u0.z; res[3]+=cU*u0.w;
      res[4]+=cU*u1.x; res[5]+=cU*u1.y; res[6]+=cU*u1.z; res[7]+=cU*u1.w;
    }
    if (cP != 0.f){
      const float4 p0 = *(const float4*)(Ph + (size_t)r*64 + tx*8);
      const float4 p1 = *(const float4*)(Ph + (size_t)r*64 + tx*8 + 4);
      res[0]+=cP*p0.x; res[1]+=cP*p0.y; res[2]+=cP*p0.z; res[3]+=cP*p0.w;
      res[4]+=cP*p1.x; res[5]+=cP*p1.y; res[6]+=cP*p1.z; res[7]+=cP*p1.w;
    }
    *(float4*)(Oh + (size_t)r*64 + tx*8)     = make_float4(res[0],res[1],res[2],res[3]);
    *(float4*)(Oh + (size_t)r*64 + tx*8 + 4) = make_float4(res[4],res[5],res[6],res[7]);
  }
}

__global__ void transpose_R(float* __restrict__ Rt, const float* __restrict__ R)
{
  const int i = blockIdx.x*256 + threadIdx.x;
  if (i < W_*WM_){
    const int w = i / WM_, m = i % WM_;
    Rt[i] = R[m*W_ + w];
  }
}

__global__ void compute_M1(float* __restrict__ M1, const float* __restrict__ B,
                           const float* __restrict__ Bt)
{
  const int i = blockIdx.x*256 + threadIdx.x;
  if (i < C_*C_){
    const int m = i >> 6, n = i & 63;
    float s = 0.f;
#pragma unroll 8
    for (int k = 0; k < C_; ++k) s += B[m*C_ + k]*Bt[k*C_ + n];
    M1[i] = s;
  }
}

// ---------------- driver ----------------------------------------------------
extern "C" void kernel_launch(void* const* d_in, const int* in_sizes, int n_in,
                              void* d_out, int out_size)
{
  const float* Y_H = (const float*)d_in[0];
  const float* Y_M = (const float*)d_in[1];
  const float* B   = (const float*)d_in[2];
  const float* B_t = (const float*)d_in[3];
  const float* R   = (const float*)d_in[4];
  float* U = (float*)d_out;

  uint4 *zA, *zB;
  float4 *X, *P;
  float *T, *M1, *Rt, *ssA, *ssB;
  cudaGetSymbolAddress((void**)&zA,  g_zA);
  cudaGetSymbolAddress((void**)&zB,  g_zB);
  cudaGetSymbolAddress((void**)&X,   g_X);
  cudaGetSymbolAddress((void**)&P,   g_P);
  cudaGetSymbolAddress((void**)&T,   g_T);
  cudaGetSymbolAddress((void**)&M1,  g_M1);
  cudaGetSymbolAddress((void**)&Rt,  g_Rt);
  cudaGetSymbolAddress((void**)&ssA, g_ssA);
  cudaGetSymbolAddress((void**)&ssB, g_ssB);

  const dim3 blk2(256);
  const dim3 grd2(H_);
  const dim3 blkG(128);

  transpose_R<<<(W_*WM_ + 255)/256, 256>>>(Rt, R);
  compute_M1 <<<(C_*C_ + 255)/256, 256>>>(M1, B, B_t);
  // P = LMBDA*(Y_H@B_t + Rt@Y_M)
  fused_x<<<dim3(4, H_), blkG>>>((float*)P, Y_H, B_t, Rt, Y_M, (const float*)X,
                                 0.f, LMBDA, 0.f);

  uint4* zbuf[2]  = { zA, zB };
  float* ssbuf[2] = { ssA, ssB };
  for (int it = 0; it < 5; ++it){
    const float4* Xp;
    if (it == 0){
      Xp = P;                                   // U = 0 -> X = P exactly
    } else {
      gemm_RU<<<H_, blkG>>>(T, R, U);
      fused_x<<<dim3(4, H_), blkG>>>((float*)X, U, M1, Rt, T, (const float*)P,
                                     1.f, -LMBDA, 1.f);
      Xp = X;
    }
    inner_step<true><<<grd2, blk2>>>(zbuf[1], zbuf[0], Xp, ssbuf[1], ssbuf[0]);
    for (int j = 1; j < 5; ++j){
      inner_step<false><<<grd2, blk2>>>(zbuf[(j-1)&1], zbuf[j&1], Xp,
                                        ssbuf[(j-1)&1], ssbuf[j&1]);
    }
    final_div<<<grd2, blk2>>>(zbuf[0], Xp, ssbuf[0], (float4*)U);
  }
}

// round 8
// speedup vs baseline: 1.3655x; 1.2568x over previous
#include <cuda_runtime.h>
#include <cuda_fp16.h>
#include <cstdint>

#define H_ 512
#define W_ 512
#define C_ 64
#define WM_ 128
#define G8_ 8                       // half8 groups per pixel (C=64 -> 8 groups)
#define C4_ 16                      // float4 per pixel
#define HWG (H_*W_*G8_)             // uint4 elements per z component plane
#define HWC4 (H_*W_*C4_)
#define LMBDA 0.1f
#define INV_LMBDA 10.0f
#define TAU 0.1f

// ---------------- scratch (static device globals; no allocations) ----------
static __device__ uint4  g_zA[2*HWG];       // z ping (half storage): [comp][h][w][g]
static __device__ uint4  g_zB[2*HWG];       // z pong
static __device__ float4 g_X [HWC4];        // X = U - lambda*grad_f(U)
static __device__ float4 g_P [HWC4];        // P = lambda*(Y_H@B_t + R^T@Y_M)
static __device__ float  g_T [H_*WM_*C_];   // T[h] = R @ U[h]
static __device__ float  g_M1[C_*C_];       // M1 = B @ B_t
static __device__ float  g_Rt[W_*WM_];      // R^T
static __device__ float  g_ssA[4*H_];       // wide partials ping [chunk][comp][h]
static __device__ float  g_ssB[4*H_];       // wide partials pong

// ---------------- F8: 8 fp32 lanes <-> half8 in one uint4 -------------------
struct F8 { float a[8]; };

__device__ __forceinline__ F8 ldz8(const uint4* __restrict__ z, int idx){
  uint4 v = z[idx];
  unsigned u[4] = {v.x, v.y, v.z, v.w};
  F8 r;
#pragma unroll
  for (int i = 0; i < 4; ++i){
    float2 f = __half22float2(*reinterpret_cast<__half2*>(&u[i]));
    r.a[2*i] = f.x; r.a[2*i+1] = f.y;
  }
  return r;
}
__device__ __forceinline__ void stz8(uint4* __restrict__ z, int idx, const F8& r){
  unsigned u[4];
#pragma unroll
  for (int i = 0; i < 4; ++i){
    __half2 h = __floats2half2_rn(r.a[2*i], r.a[2*i+1]);
    u[i] = *reinterpret_cast<unsigned*>(&h);
  }
  z[idx] = make_uint4(u[0], u[1], u[2], u[3]);
}
__device__ __forceinline__ F8 f8sub(F8 x, F8 y){ F8 r;
#pragma unroll
  for (int i=0;i<8;++i) r.a[i]=x.a[i]-y.a[i]; return r; }
__device__ __forceinline__ F8 f8neg(F8 x){ F8 r;
#pragma unroll
  for (int i=0;i<8;++i) r.a[i]=-x.a[i]; return r; }
__device__ __forceinline__ float f8dot(const F8& x){ float s=0.f;
#pragma unroll
  for (int i=0;i<8;++i) s += x.a[i]*x.a[i]; return s; }

__device__ __forceinline__ F8 ldx8(const float4* __restrict__ X, int h, int w, int g){
  const int i4 = (h*W_ + w)*C4_ + 2*g;
  const float4 p = X[i4], q = X[i4+1];
  F8 r; r.a[0]=p.x; r.a[1]=p.y; r.a[2]=p.z; r.a[3]=p.w;
        r.a[4]=q.x; r.a[5]=q.y; r.a[6]=q.z; r.a[7]=q.w;
  return r;
}

// dz components (Chambolle adjoint) on half z planes
__device__ __forceinline__ F8 dz1h(const uint4* __restrict__ z1, int h, int w, int g){
  if (h == 0)     return ldz8(z1, (0*W_ + w)*G8_ + g);
  if (h == H_-1)  return f8neg(ldz8(z1, ((H_-2)*W_ + w)*G8_ + g));
  return f8sub(ldz8(z1, (h*W_ + w)*G8_ + g), ldz8(z1, ((h-1)*W_ + w)*G8_ + g));
}
__device__ __forceinline__ F8 dz2h(const uint4* __restrict__ z2, int h, int w, int g){
  if (w == 0)     return ldz8(z2, (h*W_)*G8_ + g);
  if (w == W_-1)  return f8neg(ldz8(z2, (h*W_ + (W_-2))*G8_ + g));
  return f8sub(ldz8(z2, (h*W_ + w)*G8_ + g), ldz8(z2, (h*W_ + (w-1))*G8_ + g));
}

__device__ __forceinline__ F8 dcalc(const uint4* __restrict__ z1,
                                    const uint4* __restrict__ z2,
                                    const float4* __restrict__ X,
                                    int h, int w, int g, float s1, float s2){
  const F8 a = dz1h(z1, h, w, g);
  const F8 b = dz2h(z2, h, w, g);
  const F8 x = ldx8(X, h, w, g);
  F8 d;
#pragma unroll
  for (int i = 0; i < 8; ++i) d.a[i] = fmaf(s1, a.a[i], fmaf(s2, b.a[i], INV_LMBDA*x.a[i]));
  return d;
}
__device__ __forceinline__ F8 dcalc1(const float4* __restrict__ X, int h, int w, int g){
  const float a = (h==0)?1.f:((h==H_-1)?-1.f:0.f);
  const float b = (w==0)?1.f:((w==W_-1)?-1.f:0.f);
  const F8 x = ldx8(X, h, w, g);
  F8 d;
#pragma unroll
  for (int i = 0; i < 8; ++i) d.a[i] = fmaf(INV_LMBDA, x.a[i], a + b);
  return d;
}

// ---------------- inline projection scale (wide partial layout) -------------
// ss layout: [0,H) chunk0/comp1, [H,2H) chunk0/comp2, [2H,3H) chunk1/comp1,
// [3H,4H) chunk1/comp2. Every CTA recomputes identically (deterministic).
__device__ __forceinline__ void get_scales(const float* __restrict__ ss,
                                           float& s1, float& s2){
  __shared__ float gs1[256], gs2[256];
  const int tid = threadIdx.x;
  float v1 = 0.f, v2 = 0.f;
  for (int h = tid; h < H_; h += 256){
    v1 += sqrtf(ss[h]       + ss[2*H_ + h]);
    v2 += sqrtf(ss[H_ + h]  + ss[3*H_ + h]);
  }
  gs1[tid] = v1; gs2[tid] = v2;
  __syncthreads();
  for (int s = 128; s > 0; s >>= 1){
    if (tid < s){ gs1[tid] += gs1[tid+s]; gs2[tid] += gs2[tid+s]; }
    __syncthreads();
  }
  const float n1 = gs1[0], n2 = gs2[0];
  s1 = (n1 > 1.f) ? (1.f/n1) : 1.f;
  s2 = (n2 > 1.f) ? (1.f/n2) : 1.f;
  __syncthreads();
}

// ---------------- fused dual iteration -------------------------------------
// grid (2, H), 256 threads: half-row (256 w) per CTA.
template<bool ONES>
__global__ __launch_bounds__(256)
void inner_step(const uint4* __restrict__ zin, uint4* __restrict__ zout,
                const float4* __restrict__ Xp, const float* __restrict__ ssin,
                float* __restrict__ ssout)
{
  const int h   = blockIdx.y;
  const int w0  = blockIdx.x << 8;
  const int tid = threadIdx.x;
  const uint4* __restrict__ z1 = zin;
  const uint4* __restrict__ z2 = zin + HWG;
  float s1 = 1.f, s2 = 1.f;
  if (!ONES) get_scales(ssin, s1, s2);
  const float tt = 2.f * TAU;
  float acc1 = 0.f, acc2 = 0.f;

#pragma unroll 1
  for (int p = 0; p < 8; ++p){
    const int flat = (p << 8) + tid;       // 0..2047
    const int w  = w0 + (flat >> 3);
    const int g  = flat & 7;
    const int idx = (h*W_ + w)*G8_ + g;

    F8 d00, z1c, z2c;
    if (ONES){
      d00 = dcalc1(Xp, h, w, g);
#pragma unroll
      for (int i = 0; i < 8; ++i){ z1c.a[i] = 1.f; z2c.a[i] = 1.f; }
    } else {
      d00 = dcalc(z1, z2, Xp, h, w, g, s1, s2);
      const F8 za = ldz8(z1, idx), zb = ldz8(z2, idx);
#pragma unroll
      for (int i = 0; i < 8; ++i){ z1c.a[i] = s1*za.a[i]; z2c.a[i] = s2*zb.a[i]; }
    }

    F8 w1o = z1c, w2o = z2c;
    if (h < H_-1){
      const F8 dn = ONES ? dcalc1(Xp, h+1, w, g)
                         : dcalc(z1, z2, Xp, h+1, w, g, s1, s2);
#pragma unroll
      for (int i = 0; i < 8; ++i) w1o.a[i] = fmaf(tt, dn.a[i]-d00.a[i], z1c.a[i]);
    }
    if (w < W_-1){
      const F8 de = ONES ? dcalc1(Xp, h, w+1, g)
                         : dcalc(z1, z2, Xp, h, w+1, g, s1, s2);
#pragma unroll
      for (int i = 0; i < 8; ++i) w2o.a[i] = fmaf(tt, de.a[i]-d00.a[i], z2c.a[i]);
    }

    stz8(zout, idx, w1o);
    stz8(zout + HWG, idx, w2o);
    acc1 += f8dot(w1o);
    acc2 += f8dot(w2o);
  }

  __shared__ float sm1[256], sm2[256];
  sm1[tid] = acc1; sm2[tid] = acc2;
  __syncthreads();
  for (int s = 128; s > 0; s >>= 1){
    if (tid < s){ sm1[tid] += sm1[tid+s]; sm2[tid] += sm2[tid+s]; }
    __syncthreads();
  }
  if (tid == 0){
    const int base = blockIdx.x ? 2*H_ : 0;   // disjoint slots per chunk
    ssout[base + h]       = sm1[0];
    ssout[base + H_ + h]  = sm2[0];
  }
}

// proxg output: U = X + LMBDA * div(s .* z)
__global__ __launch_bounds__(256)
void final_div(const uint4* __restrict__ zin, const float4* __restrict__ Xp,
               const float* __restrict__ ssin, float4* __restrict__ U)
{
  const int h   = blockIdx.y;
  const int w0  = blockIdx.x << 8;
  const int tid = threadIdx.x;
  const uint4* __restrict__ z1 = zin;
  const uint4* __restrict__ z2 = zin + HWG;
  float s1, s2;
  get_scales(ssin, s1, s2);
#pragma unroll 1
  for (int p = 0; p < 8; ++p){
    const int flat = (p << 8) + tid;
    const int w  = w0 + (flat >> 3);
    const int g  = flat & 7;
    const F8 a = dz1h(z1, h, w, g);
    const F8 b = dz2h(z2, h, w, g);
    const F8 x = ldx8(Xp, h, w, g);
    F8 r;
#pragma unroll
    for (int i = 0; i < 8; ++i)
      r.a[i] = fmaf(LMBDA, fmaf(s1, a.a[i], s2*b.a[i]), x.a[i]);
    const int i4 = (h*W_ + w)*C4_ + 2*g;
    U[i4]   = make_float4(r.a[0], r.a[1], r.a[2], r.a[3]);
    U[i4+1] = make_float4(r.a[4], r.a[5], r.a[6], r.a[7]);
  }
}

// ---------------- tf32 tensor-core GEMM (3xTF32 split) ----------------------
__device__ __forceinline__ uint32_t to_tf32(float v){
  uint32_t r; asm("cvt.rna.tf32.f32 %0, %1;" : "=r"(r) : "f"(v)); return r;
}
__device__ __forceinline__ void mma_tf32(float (&c)[4], const uint32_t* a,
                                         const uint32_t* b){
  asm volatile(
    "mma.sync.aligned.m16n8k8.row.col.f32.tf32.tf32.f32 "
    "{%0,%1,%2,%3}, {%4,%5,%6,%7}, {%8,%9}, {%0,%1,%2,%3};"
    : "+f"(c[0]), "+f"(c[1]), "+f"(c[2]), "+f"(c[3])
    : "r"(a[0]), "r"(a[1]), "r"(a[2]), "r"(a[3]), "r"(b[0]), "r"(b[1]));
}

#define SA 36                      // A smem stride
#define SB 68                      // B smem stride
#define SMEM_TC ((128*SA*2 + 32*SB*2)*4)

// out[h][m0:m0+128, 0:64] = cU*Uin + cMM*( [do_p1] Uin@N1  +  A2@Bin[h] ) + cP*Pb
// Uin/Pb h-stride 32768 (H,W,C tensors); A2: rows m0.., lda=K2; Bin: per-h K2x64.
__global__ __launch_bounds__(256)
void gemm_tc(float* __restrict__ out, int out_h,
             const float* __restrict__ Uin,
             const float* __restrict__ N1,
             const float* __restrict__ A2,
             const float* __restrict__ Bin, int bin_h,
             const float* __restrict__ Pb,
             int K2, int do_p1, float cU, float cMM, float cP)
{
  extern __shared__ float smem[];
  float* Ah = smem;                 // [128][SA]
  float* Al = Ah + 128*SA;
  float* Bh = Al + 128*SA;          // [32][SB]
  float* Bl = Bh + 32*SB;

  const int h   = blockIdx.y;
  const int m0  = blockIdx.x << 7;
  const int tid = threadIdx.x;
  const int lane = tid & 31, wid = tid >> 5;
  const int wm = wid & 3, wn = wid >> 2;      // 4 x 2 warps over (128m, 64n)
  const int gid = lane >> 2, t4 = lane & 3;

  float acc[2][4][4];
#pragma unroll
  for (int i = 0; i < 2; ++i)
#pragma unroll
    for (int j = 0; j < 4; ++j)
#pragma unroll
      for (int q = 0; q < 4; ++q) acc[i][j][q] = 0.f;

  for (int ph = 0; ph < 2; ++ph){
    const float* Ag; int lda; const float* Bg; int Kp;
    if (ph == 0){
      if (!do_p1) continue;
      Ag = Uin + (size_t)h*32768 + (size_t)m0*64; lda = 64; Bg = N1; Kp = 64;
    } else {
      Ag = A2 + (size_t)m0*K2; lda = K2; Bg = Bin + (size_t)h*bin_h; Kp = K2;
    }
    for (int k0 = 0; k0 < Kp; k0 += 32){
      __syncthreads();
      // fill A chunk 128x32 (hi/lo split)
      {
        const int row0 = tid >> 3;            // 0..31
        const int k4   = (tid & 7) << 2;
#pragma unroll
        for (int r = 0; r < 4; ++r){
          const int row = row0 + 32*r;
          const float4 v = *(const float4*)(Ag + (size_t)row*lda + k0 + k4);
          const float vv[4] = {v.x, v.y, v.z, v.w};
#pragma unroll
          for (int j = 0; j < 4; ++j){
            const float hi = __uint_as_float(to_tf32(vv[j]));
            const float lo = __uint_as_float(to_tf32(vv[j] - hi));
            Ah[row*SA + k4 + j] = hi;
            Al[row*SA + k4 + j] = lo;
          }
        }
      }
      // fill B chunk 32x64 (hi/lo split)
      {
        const int kk0 = tid >> 4;             // 0..15
        const int n4  = (tid & 15) << 2;
#pragma unroll
        for (int r = 0; r < 2; ++r){
          const int k = kk0 + 16*r;
          const float4 v = *(const float4*)(Bg + (size_t)(k0+k)*64 + n4);
          const float vv[4] = {v.x, v.y, v.z, v.w};
#pragma unroll
          for (int j = 0; j < 4; ++j){
            const float hi = __uint_as_float(to_tf32(vv[j]));
            const float lo = __uint_as_float(to_tf32(vv[j] - hi));
            Bh[k*SB + n4 + j] = hi;
            Bl[k*SB + n4 + j] = lo;
          }
        }
      }
      __syncthreads();
#pragma unroll
      for (int kf = 0; kf < 4; ++kf){
        uint32_t ah[2][4], al[2][4];
#pragma unroll
        for (int fm = 0; fm < 2; ++fm){
          const int r0 = wm*32 + fm*16 + gid;
          const int c0 = kf*8 + t4;
          ah[fm][0] = __float_as_uint(Ah[r0*SA + c0]);
          ah[fm][1] = __float_as_uint(Ah[(r0+8)*SA + c0]);
          ah[fm][2] = __float_as_uint(Ah[r0*SA + c0 + 4]);
          ah[fm][3] = __float_as_uint(Ah[(r0+8)*SA + c0 + 4]);
          al[fm][0] = __float_as_uint(Al[r0*SA + c0]);
          al[fm][1] = __float_as_uint(Al[(r0+8)*SA + c0]);
          al[fm][2] = __float_as_uint(Al[r0*SA + c0 + 4]);
          al[fm][3] = __float_as_uint(Al[(r0+8)*SA + c0 + 4]);
        }
        uint32_t bh[4][2], bl[4][2];
#pragma unroll
        for (int fn = 0; fn < 4; ++fn){
          const int n = wn*32 + fn*8 + gid;
          const int k = kf*8 + t4;
          bh[fn][0] = __float_as_uint(Bh[k*SB + n]);
          bh[fn][1] = __float_as_uint(Bh[(k+4)*SB + n]);
          bl[fn][0] = __float_as_uint(Bl[k*SB + n]);
          bl[fn][1] = __float_as_uint(Bl[(k+4)*SB + n]);
        }
#pragma unroll
        for (int fm = 0; fm < 2; ++fm)
#pragma unroll
          for (int fn = 0; fn < 4; ++fn){
            mma_tf32(acc[fm][fn], ah[fm], bh[fn]);   // hi*hi
            mma_tf32(acc[fm][fn], ah[fm], bl[fn]);   // hi*lo
            mma_tf32(acc[fm][fn], al[fm], bh[fn]);   // lo*hi
          }
      }
    }
  }

  // epilogue
  float* Oh = out + (size_t)h*out_h;
  const float* Uh = Uin + (size_t)h*32768;
  const float* Ph = Pb  + (size_t)h*32768;
#pragma unroll
  for (int fm = 0; fm < 2; ++fm){
#pragma unroll
    for (int fn = 0; fn < 4; ++fn){
      const int r0 = m0 + wm*32 + fm*16 + gid;
      const int c0 = wn*32 + fn*8 + 2*t4;
#pragma unroll
      for (int half = 0; half < 2; ++half){
        const int r = r0 + 8*half;
        float v0 = cMM * acc[fm][fn][2*half];
        float v1 = cMM * acc[fm][fn][2*half + 1];
        if (cU != 0.f){
          const float2 u = *(const float2*)(Uh + (size_t)r*64 + c0);
          v0 += cU*u.x; v1 += cU*u.y;
        }
        if (cP != 0.f){
          const float2 pv = *(const float2*)(Ph + (size_t)r*64 + c0);
          v0 += cP*pv.x; v1 += cP*pv.y;
        }
        *(float2*)(Oh + (size_t)r*64 + c0) = make_float2(v0, v1);
      }
    }
  }
}

__global__ void transpose_R(float* __restrict__ Rt, const float* __restrict__ R)
{
  const int i = blockIdx.x*256 + threadIdx.x;
  if (i < W_*WM_){
    const int w = i / WM_, m = i % WM_;
    Rt[i] = R[m*W_ + w];
  }
}

__global__ void compute_M1(float* __restrict__ M1, const float* __restrict__ B,
                           const float* __restrict__ Bt)
{
  const int i = blockIdx.x*256 + threadIdx.x;
  if (i < C_*C_){
    const int m = i >> 6, n = i & 63;
    float s = 0.f;
#pragma unroll 8
    for (int k = 0; k < C_; ++k) s += B[m*C_ + k]*Bt[k*C_ + n];
    M1[i] = s;
  }
}

// ---------------- driver ----------------------------------------------------
extern "C" void kernel_launch(void* const* d_in, const int* in_sizes, int n_in,
                              void* d_out, int out_size)
{
  const float* Y_H = (const float*)d_in[0];
  const float* Y_M = (const float*)d_in[1];
  const float* B   = (const float*)d_in[2];
  const float* B_t = (const float*)d_in[3];
  const float* R   = (const float*)d_in[4];
  float* U = (float*)d_out;

  uint4 *zA, *zB;
  float4 *X, *P;
  float *T, *M1, *Rt, *ssA, *ssB;
  cudaGetSymbolAddress((void**)&zA,  g_zA);
  cudaGetSymbolAddress((void**)&zB,  g_zB);
  cudaGetSymbolAddress((void**)&X,   g_X);
  cudaGetSymbolAddress((void**)&P,   g_P);
  cudaGetSymbolAddress((void**)&T,   g_T);
  cudaGetSymbolAddress((void**)&M1,  g_M1);
  cudaGetSymbolAddress((void**)&Rt,  g_Rt);
  cudaGetSymbolAddress((void**)&ssA, g_ssA);
  cudaGetSymbolAddress((void**)&ssB, g_ssB);

  cudaFuncSetAttribute(gemm_tc, cudaFuncAttributeMaxDynamicSharedMemorySize,
                       SMEM_TC);

  const dim3 blk2(256);
  const dim3 grd2(2, H_);

  transpose_R<<<(W_*WM_ + 255)/256, 256>>>(Rt, R);
  compute_M1 <<<(C_*C_ + 255)/256, 256>>>(M1, B, B_t);
  // P = LMBDA*(Y_H@B_t + Rt@Y_M)
  gemm_tc<<<dim3(4, H_), 256, SMEM_TC>>>((float*)P, 32768,
                                         Y_H, B_t, Rt, Y_M, WM_*C_,
                                         (const float*)P,
                                         WM_, 1, 0.f, LMBDA, 0.f);

  uint4* zbuf[2]  = { zA, zB };
  float* ssbuf[2] = { ssA, ssB };
  for (int it = 0; it < 5; ++it){
    const float4* Xp;
    if (it == 0){
      Xp = P;                                   // U = 0 -> X = P exactly
    } else {
      // T[h] = R @ U[h]
      gemm_tc<<<dim3(1, H_), 256, SMEM_TC>>>(T, WM_*C_,
                                             U, M1, R, U, W_*C_,
                                             (const float*)P,
                                             W_, 0, 0.f, 1.f, 0.f);
      // X = U - LMBDA*(U@M1 + Rt@T) + P
      gemm_tc<<<dim3(4, H_), 256, SMEM_TC>>>((float*)X, 32768,
                                             U, M1, Rt, T, WM_*C_,
                                             (const float*)P,
                                             WM_, 1, 1.f, -LMBDA, 1.f);
      Xp = X;
    }
    inner_step<true><<<grd2, blk2>>>(zbuf[1], zbuf[0], Xp, ssbuf[1], ssbuf[0]);
    for (int j = 1; j < 5; ++j){
      inner_step<false><<<grd2, blk2>>>(zbuf[(j-1)&1], zbuf[j&1], Xp,
                                        ssbuf[(j-1)&1], ssbuf[j&1]);
    }
    final_div<<<grd2, blk2>>>(zbuf[0], Xp, ssbuf[0], (float4*)U);
  }
}

// round 9
// speedup vs baseline: 1.7730x; 1.2985x over previous
#include <cuda_runtime.h>
#include <cuda_fp16.h>
#include <cstdint>

#define H_ 512
#define W_ 512
#define C_ 64
#define WM_ 128
#define G8_ 8                       // half8 groups per pixel (C=64 -> 8 groups)
#define C4_ 16                      // float4 per pixel
#define HWG (H_*W_*G8_)             // uint4 elements per z component plane
#define HWC4 (H_*W_*C4_)
#define LMBDA 0.1f
#define INV_LMBDA 10.0f
#define TAU 0.1f

// ---------------- scratch (static device globals; no allocations) ----------
static __device__ uint4  g_zA[2*HWG];       // z ping (half): [comp][h][w][g]
static __device__ uint4  g_zB[2*HWG];       // z pong
static __device__ float4 g_X [HWC4];        // X = U - lambda*grad_f(U)   (fp32)
static __device__ float4 g_P [HWC4];        // P = lambda*(Y_H@B_t + R^T@Y_M)
static __device__ uint4  g_Xh[HWG];         // 10*X in half8 (stencil operand)
static __device__ uint4  g_Ph[HWG];         // 10*P in half8
static __device__ float  g_T [H_*WM_*C_];   // T[h] = R @ U[h]
static __device__ float  g_M1[C_*C_];       // M1 = B @ B_t
static __device__ float  g_Rt[W_*WM_];      // R^T
static __device__ float  g_ssA[4*H_];       // wide partials ping [chunk][comp][h]
static __device__ float  g_ssB[4*H_];       // wide partials pong

// ---------------- half8 (H8) utilities --------------------------------------
struct H8 { __half2 h[4]; };

__device__ __forceinline__ __half2 u2h(unsigned u){
  __half2 r; *reinterpret_cast<unsigned*>(&r) = u; return r;
}
__device__ __forceinline__ unsigned h2u(__half2 h){
  return *reinterpret_cast<unsigned*>(&h);
}
__device__ __forceinline__ H8 ld8h(const uint4* __restrict__ p, int idx){
  const uint4 v = p[idx];
  H8 r; r.h[0]=u2h(v.x); r.h[1]=u2h(v.y); r.h[2]=u2h(v.z); r.h[3]=u2h(v.w);
  return r;
}
__device__ __forceinline__ void st8h(uint4* __restrict__ p, int idx, const H8& r){
  p[idx] = make_uint4(h2u(r.h[0]), h2u(r.h[1]), h2u(r.h[2]), h2u(r.h[3]));
}
__device__ __forceinline__ H8 h8sub(H8 a, H8 b){ H8 r;
#pragma unroll
  for (int i=0;i<4;++i) r.h[i]=__hsub2(a.h[i],b.h[i]); return r; }
__device__ __forceinline__ H8 h8neg(H8 a){ H8 r;
#pragma unroll
  for (int i=0;i<4;++i) r.h[i]=__hneg2(a.h[i]); return r; }

// dz components (Chambolle adjoint), half arithmetic
__device__ __forceinline__ H8 dz1(const uint4* __restrict__ z1, int h, int w, int g){
  if (h == 0)     return ld8h(z1, w*G8_ + g);
  if (h == H_-1)  return h8neg(ld8h(z1, ((H_-2)*W_ + w)*G8_ + g));
  return h8sub(ld8h(z1, (h*W_ + w)*G8_ + g), ld8h(z1, ((h-1)*W_ + w)*G8_ + g));
}
__device__ __forceinline__ H8 dz2(const uint4* __restrict__ z2, int h, int w, int g){
  if (w == 0)     return ld8h(z2, (h*W_)*G8_ + g);
  if (w == W_-1)  return h8neg(ld8h(z2, (h*W_ + (W_-2))*G8_ + g));
  return h8sub(ld8h(z2, (h*W_ + w)*G8_ + g), ld8h(z2, (h*W_ + (w-1))*G8_ + g));
}

// d = s1*dz1 + s2*dz2 + Xh (Xh pre-scaled by 1/lambda)
__device__ __forceinline__ H8 dcalc(const uint4* __restrict__ z1,
                                    const uint4* __restrict__ z2,
                                    const uint4* __restrict__ Xh,
                                    int h, int w, int g, __half2 s1h, __half2 s2h){
  const H8 a = dz1(z1, h, w, g);
  const H8 b = dz2(z2, h, w, g);
  const H8 x = ld8h(Xh, (h*W_ + w)*G8_ + g);
  H8 d;
#pragma unroll
  for (int i=0;i<4;++i)
    d.h[i] = __hfma2(s1h, a.h[i], __hfma2(s2h, b.h[i], x.h[i]));
  return d;
}
// ONES variant: z == 1 -> dz terms are edge constants
__device__ __forceinline__ H8 dcalc1(const uint4* __restrict__ Xh, int h, int w, int g){
  const float a = (h==0)?1.f:((h==H_-1)?-1.f:0.f);
  const float b = (w==0)?1.f:((w==W_-1)?-1.f:0.f);
  const __half2 e = __float2half2_rn(a + b);
  const H8 x = ld8h(Xh, (h*W_ + w)*G8_ + g);
  H8 d;
#pragma unroll
  for (int i=0;i<4;++i) d.h[i] = __hadd2(x.h[i], e);
  return d;
}

// ---------------- fp32 helpers for final_div --------------------------------
struct F8 { float a[8]; };
__device__ __forceinline__ F8 h8f(const H8& x){
  F8 r;
#pragma unroll
  for (int i=0;i<4;++i){
    const float2 f = __half22float2(x.h[i]);
    r.a[2*i] = f.x; r.a[2*i+1] = f.y;
  }
  return r;
}

// ---------------- inline projection scale (wide partial layout) -------------
// ss layout: [0,H) c0/comp1, [H,2H) c0/comp2, [2H,3H) c1/comp1, [3H,4H) c1/comp2
__device__ __forceinline__ void get_scales(const float* __restrict__ ss,
                                           float& s1, float& s2){
  __shared__ float gs1[256], gs2[256];
  const int tid = threadIdx.x;
  float v1 = 0.f, v2 = 0.f;
  for (int h = tid; h < H_; h += 256){
    v1 += sqrtf(ss[h]       + ss[2*H_ + h]);
    v2 += sqrtf(ss[H_ + h]  + ss[3*H_ + h]);
  }
  gs1[tid] = v1; gs2[tid] = v2;
  __syncthreads();
  for (int s = 128; s > 0; s >>= 1){
    if (tid < s){ gs1[tid] += gs1[tid+s]; gs2[tid] += gs2[tid+s]; }
    __syncthreads();
  }
  const float n1 = gs1[0], n2 = gs2[0];
  s1 = (n1 > 1.f) ? (1.f/n1) : 1.f;
  s2 = (n2 > 1.f) ? (1.f/n2) : 1.f;
  __syncthreads();
}

// ---------------- fused dual iteration (all-half2 math) ---------------------
// grid (2, H), 256 threads; half-row (256 w) per CTA.
template<bool ONES>
__global__ __launch_bounds__(256)
void inner_step(const uint4* __restrict__ zin, uint4* __restrict__ zout,
                const uint4* __restrict__ Xh, const float* __restrict__ ssin,
                float* __restrict__ ssout)
{
  const int h   = blockIdx.y;
  const int w0  = blockIdx.x << 8;
  const int tid = threadIdx.x;
  const uint4* __restrict__ z1 = zin;
  const uint4* __restrict__ z2 = zin + HWG;
  float s1 = 1.f, s2 = 1.f;
  if (!ONES) get_scales(ssin, s1, s2);
  const __half2 s1h = __float2half2_rn(s1);
  const __half2 s2h = __float2half2_rn(s2);
  const __half2 tth = __float2half2_rn(2.f * TAU);
  const __half2 one = __float2half2_rn(1.f);
  float acc1 = 0.f, acc2 = 0.f;

#pragma unroll 1
  for (int p = 0; p < 8; ++p){
    const int flat = (p << 8) + tid;       // 0..2047
    const int w  = w0 + (flat >> 3);
    const int g  = flat & 7;
    const int idx = (h*W_ + w)*G8_ + g;

    H8 d00, z1c, z2c;
    if (ONES){
      d00 = dcalc1(Xh, h, w, g);
#pragma unroll
      for (int i=0;i<4;++i){ z1c.h[i] = one; z2c.h[i] = one; }
    } else {
      d00 = dcalc(z1, z2, Xh, h, w, g, s1h, s2h);
      const H8 za = ld8h(z1, idx), zb = ld8h(z2, idx);
#pragma unroll
      for (int i=0;i<4;++i){
        z1c.h[i] = __hmul2(s1h, za.h[i]);
        z2c.h[i] = __hmul2(s2h, zb.h[i]);
      }
    }

    H8 w1o = z1c, w2o = z2c;
    if (h < H_-1){
      const H8 dn = ONES ? dcalc1(Xh, h+1, w, g)
                         : dcalc(z1, z2, Xh, h+1, w, g, s1h, s2h);
#pragma unroll
      for (int i=0;i<4;++i)
        w1o.h[i] = __hfma2(tth, __hsub2(dn.h[i], d00.h[i]), z1c.h[i]);
    }
    if (w < W_-1){
      const H8 de = ONES ? dcalc1(Xh, h, w+1, g)
                         : dcalc(z1, z2, Xh, h, w+1, g, s1h, s2h);
#pragma unroll
      for (int i=0;i<4;++i)
        w2o.h[i] = __hfma2(tth, __hsub2(de.h[i], d00.h[i]), z2c.h[i]);
    }

    st8h(zout, idx, w1o);
    st8h(zout + HWG, idx, w2o);
#pragma unroll
    for (int i=0;i<4;++i){
      const float2 f1 = __half22float2(w1o.h[i]);
      const float2 f2 = __half22float2(w2o.h[i]);
      acc1 += f1.x*f1.x + f1.y*f1.y;
      acc2 += f2.x*f2.x + f2.y*f2.y;
    }
  }

  __shared__ float sm1[256], sm2[256];
  sm1[tid] = acc1; sm2[tid] = acc2;
  __syncthreads();
  for (int s = 128; s > 0; s >>= 1){
    if (tid < s){ sm1[tid] += sm1[tid+s]; sm2[tid] += sm2[tid+s]; }
    __syncthreads();
  }
  if (tid == 0){
    const int base = blockIdx.x ? 2*H_ : 0;   // disjoint slots per chunk
    ssout[base + h]       = sm1[0];
    ssout[base + H_ + h]  = sm2[0];
  }
}

// proxg output: U = X + LMBDA * div(s .* z)   (fp32 base, fp32 epilogue)
__global__ __launch_bounds__(256)
void final_div(const uint4* __restrict__ zin, const float4* __restrict__ Xp,
               const float* __restrict__ ssin, float4* __restrict__ U)
{
  const int h   = blockIdx.y;
  const int w0  = blockIdx.x << 8;
  const int tid = threadIdx.x;
  const uint4* __restrict__ z1 = zin;
  const uint4* __restrict__ z2 = zin + HWG;
  float s1, s2;
  get_scales(ssin, s1, s2);
#pragma unroll 1
  for (int p = 0; p < 8; ++p){
    const int flat = (p << 8) + tid;
    const int w  = w0 + (flat >> 3);
    const int g  = flat & 7;
    const F8 a = h8f(dz1(z1, h, w, g));
    const F8 b = h8f(dz2(z2, h, w, g));
    const int i4 = (h*W_ + w)*C4_ + 2*g;
    const float4 xp = Xp[i4], xq = Xp[i4+1];
    const float xv[8] = {xp.x,xp.y,xp.z,xp.w, xq.x,xq.y,xq.z,xq.w};
    float r[8];
#pragma unroll
    for (int i = 0; i < 8; ++i)
      r[i] = fmaf(LMBDA, fmaf(s1, a.a[i], s2*b.a[i]), xv[i]);
    U[i4]   = make_float4(r[0], r[1], r[2], r[3]);
    U[i4+1] = make_float4(r[4], r[5], r[6], r[7]);
  }
}

// ---------------- tf32 tensor-core GEMM (2-term split) ----------------------
__device__ __forceinline__ uint32_t to_tf32(float v){
  uint32_t r; asm("cvt.rna.tf32.f32 %0, %1;" : "=r"(r) : "f"(v)); return r;
}
__device__ __forceinline__ void mma_tf32(float (&c)[4], const uint32_t* a,
                                         const uint32_t* b){
  asm volatile(
    "mma.sync.aligned.m16n8k8.row.col.f32.tf32.tf32.f32 "
    "{%0,%1,%2,%3}, {%4,%5,%6,%7}, {%8,%9}, {%0,%1,%2,%3};"
    : "+f"(c[0]), "+f"(c[1]), "+f"(c[2]), "+f"(c[3])
    : "r"(a[0]), "r"(a[1]), "r"(a[2]), "r"(a[3]), "r"(b[0]), "r"(b[1]));
}

#define SA 36                      // A smem stride
#define SB 68                      // B smem stride
#define SMEM_TC ((128*SA + 32*SB*2)*4)

// out[h][m0:m0+128, 0:64] = cU*Uin + cMM*( [do_p1] Uin@N1  +  A2@Bin[h] ) + cP*Pb
// If outh != nullptr, also writes INV_LMBDA*result to the half8 buffer.
__global__ __launch_bounds__(256)
void gemm_tc(float* __restrict__ out, int out_h, __half* __restrict__ outh,
             const float* __restrict__ Uin,
             const float* __restrict__ N1,
             const float* __restrict__ A2,
             const float* __restrict__ Bin, int bin_h,
             const float* __restrict__ Pb,
             int K2, int do_p1, float cU, float cMM, float cP)
{
  extern __shared__ float smem[];
  float* Ah = smem;                 // [128][SA]  (hi only)
  float* Bh = Ah + 128*SA;          // [32][SB]
  float* Bl = Bh + 32*SB;

  const int h   = blockIdx.y;
  const int m0  = blockIdx.x << 7;
  const int tid = threadIdx.x;
  const int lane = tid & 31, wid = tid >> 5;
  const int wm = wid & 3, wn = wid >> 2;      // 4 x 2 warps over (128m, 64n)
  const int gid = lane >> 2, t4 = lane & 3;

  float acc[2][4][4];
#pragma unroll
  for (int i = 0; i < 2; ++i)
#pragma unroll
    for (int j = 0; j < 4; ++j)
#pragma unroll
      for (int q = 0; q < 4; ++q) acc[i][j][q] = 0.f;

  for (int ph = 0; ph < 2; ++ph){
    const float* Ag; int lda; const float* Bg; int Kp;
    if (ph == 0){
      if (!do_p1) continue;
      Ag = Uin + (size_t)h*32768 + (size_t)m0*64; lda = 64; Bg = N1; Kp = 64;
    } else {
      Ag = A2 + (size_t)m0*K2; lda = K2; Bg = Bin + (size_t)h*bin_h; Kp = K2;
    }
    for (int k0 = 0; k0 < Kp; k0 += 32){
      __syncthreads();
      // fill A chunk 128x32 (hi only)
      {
        const int row0 = tid >> 3;            // 0..31
        const int k4   = (tid & 7) << 2;
#pragma unroll
        for (int r = 0; r < 4; ++r){
          const int row = row0 + 32*r;
          const float4 v = *(const float4*)(Ag + (size_t)row*lda + k0 + k4);
          const float vv[4] = {v.x, v.y, v.z, v.w};
#pragma unroll
          for (int j = 0; j < 4; ++j)
            Ah[row*SA + k4 + j] = __uint_as_float(to_tf32(vv[j]));
        }
      }
      // fill B chunk 32x64 (hi/lo split)
      {
        const int kk0 = tid >> 4;             // 0..15
        const int n4  = (tid & 15) << 2;
#pragma unroll
        for (int r = 0; r < 2; ++r){
          const int k = kk0 + 16*r;
          const float4 v = *(const float4*)(Bg + (size_t)(k0+k)*64 + n4);
          const float vv[4] = {v.x, v.y, v.z, v.w};
#pragma unroll
          for (int j = 0; j < 4; ++j){
            const float hi = __uint_as_float(to_tf32(vv[j]));
            Bh[k*SB + n4 + j] = hi;
            Bl[k*SB + n4 + j] = __uint_as_float(to_tf32(vv[j] - hi));
          }
        }
      }
      __syncthreads();
#pragma unroll
      for (int kf = 0; kf < 4; ++kf){
        uint32_t ah[2][4];
#pragma unroll
        for (int fm = 0; fm < 2; ++fm){
          const int r0 = wm*32 + fm*16 + gid;
          const int c0 = kf*8 + t4;
          ah[fm][0] = __float_as_uint(Ah[r0*SA + c0]);
          ah[fm][1] = __float_as_uint(Ah[(r0+8)*SA + c0]);
          ah[fm][2] = __float_as_uint(Ah[r0*SA + c0 + 4]);
          ah[fm][3] = __float_as_uint(Ah[(r0+8)*SA + c0 + 4]);
        }
        uint32_t bh[4][2], bl[4][2];
#pragma unroll
        for (int fn = 0; fn < 4; ++fn){
          const int n = wn*32 + fn*8 + gid;
          const int k = kf*8 + t4;
          bh[fn][0] = __float_as_uint(Bh[k*SB + n]);
          bh[fn][1] = __float_as_uint(Bh[(k+4)*SB + n]);
          bl[fn][0] = __float_as_uint(Bl[k*SB + n]);
          bl[fn][1] = __float_as_uint(Bl[(k+4)*SB + n]);
        }
#pragma unroll
        for (int fm = 0; fm < 2; ++fm)
#pragma unroll
          for (int fn = 0; fn < 4; ++fn){
            mma_tf32(acc[fm][fn], ah[fm], bh[fn]);   // hi*hi
            mma_tf32(acc[fm][fn], ah[fm], bl[fn]);   // hi*lo
          }
      }
    }
  }

  // epilogue
  float* Oh = out + (size_t)h*out_h;
  __half* Ohh = outh ? (outh + (size_t)h*out_h) : nullptr;
  const float* Uh = Uin + (size_t)h*32768;
  const float* Ph = Pb  + (size_t)h*32768;
#pragma unroll
  for (int fm = 0; fm < 2; ++fm){
#pragma unroll
    for (int fn = 0; fn < 4; ++fn){
      const int r0 = m0 + wm*32 + fm*16 + gid;
      const int c0 = wn*32 + fn*8 + 2*t4;
#pragma unroll
      for (int half = 0; half < 2; ++half){
        const int r = r0 + 8*half;
        float v0 = cMM * acc[fm][fn][2*half];
        float v1 = cMM * acc[fm][fn][2*half + 1];
        if (cU != 0.f){
          const float2 u = *(const float2*)(Uh + (size_t)r*64 + c0);
          v0 += cU*u.x; v1 += cU*u.y;
        }
        if (cP != 0.f){
          const float2 pv = *(const float2*)(Ph + (size_t)r*64 + c0);
          v0 += cP*pv.x; v1 += cP*pv.y;
        }
        *(float2*)(Oh + (size_t)r*64 + c0) = make_float2(v0, v1);
        if (Ohh)
          *reinterpret_cast<__half2*>(Ohh + (size_t)r*64 + c0) =
            __floats2half2_rn(INV_LMBDA*v0, INV_LMBDA*v1);
      }
    }
  }
}

__global__ void transpose_R(float* __restrict__ Rt, const float* __restrict__ R)
{
  const int i = blockIdx.x*256 + threadIdx.x;
  if (i < W_*WM_){
    const int w = i / WM_, m = i % WM_;
    Rt[i] = R[m*W_ + w];
  }
}

__global__ void compute_M1(float* __restrict__ M1, const float* __restrict__ B,
                           const float* __restrict__ Bt)
{
  const int i = blockIdx.x*256 + threadIdx.x;
  if (i < C_*C_){
    const int m = i >> 6, n = i & 63;
    float s = 0.f;
#pragma unroll 8
    for (int k = 0; k < C_; ++k) s += B[m*C_ + k]*Bt[k*C_ + n];
    M1[i] = s;
  }
}

// ---------------- driver ----------------------------------------------------
extern "C" void kernel_launch(void* const* d_in, const int* in_sizes, int n_in,
                              void* d_out, int out_size)
{
  const float* Y_H = (const float*)d_in[0];
  const float* Y_M = (const float*)d_in[1];
  const float* B   = (const float*)d_in[2];
  const float* B_t = (const float*)d_in[3];
  const float* R   = (const float*)d_in[4];
  float* U = (float*)d_out;

  uint4 *zA, *zB, *Xh, *Ph;
  float4 *X, *P;
  float *T, *M1, *Rt, *ssA, *ssB;
  cudaGetSymbolAddress((void**)&zA,  g_zA);
  cudaGetSymbolAddress((void**)&zB,  g_zB);
  cudaGetSymbolAddress((void**)&X,   g_X);
  cudaGetSymbolAddress((void**)&P,   g_P);
  cudaGetSymbolAddress((void**)&Xh,  g_Xh);
  cudaGetSymbolAddress((void**)&Ph,  g_Ph);
  cudaGetSymbolAddress((void**)&T,   g_T);
  cudaGetSymbolAddress((void**)&M1,  g_M1);
  cudaGetSymbolAddress((void**)&Rt,  g_Rt);
  cudaGetSymbolAddress((void**)&ssA, g_ssA);
  cudaGetSymbolAddress((void**)&ssB, g_ssB);

  cudaFuncSetAttribute(gemm_tc, cudaFuncAttributeMaxDynamicSharedMemorySize,
                       SMEM_TC);

  const dim3 blk2(256);
  const dim3 grd2(2, H_);

  transpose_R<<<(W_*WM_ + 255)/256, 256>>>(Rt, R);
  compute_M1 <<<(C_*C_ + 255)/256, 256>>>(M1, B, B_t);
  // P = LMBDA*(Y_H@B_t + Rt@Y_M), plus Ph = 10*P in half
  gemm_tc<<<dim3(4, H_), 256, SMEM_TC>>>((float*)P, 32768, (__half*)Ph,
                                         Y_H, B_t, Rt, Y_M, WM_*C_,
                                         (const float*)P,
                                         WM_, 1, 0.f, LMBDA, 0.f);

  uint4* zbuf[2]  = { zA, zB };
  float* ssbuf[2] = { ssA, ssB };
  for (int it = 0; it < 5; ++it){
    const uint4* Xhp;
    const float4* Xp;
    if (it == 0){
      Xhp = Ph; Xp = P;                         // U = 0 -> X = P exactly
    } else {
      // T[h] = R @ U[h]
      gemm_tc<<<dim3(1, H_), 256, SMEM_TC>>>(T, WM_*C_, (__half*)nullptr,
                                             U, M1, R, U, W_*C_,
                                             (const float*)P,
                                             W_, 0, 0.f, 1.f, 0.f);
      // X = U - LMBDA*(U@M1 + Rt@T) + P, plus Xh = 10*X in half
      gemm_tc<<<dim3(4, H_), 256, SMEM_TC>>>((float*)X, 32768, (__half*)Xh,
                                             U, M1, Rt, T, WM_*C_,
                                             (const float*)P,
                                             WM_, 1, 1.f, -LMBDA, 1.f);
      Xhp = Xh; Xp = X;
    }
    inner_step<true><<<grd2, blk2>>>(zbuf[1], zbuf[0], Xhp, ssbuf[1], ssbuf[0]);
    for (int j = 1; j < 5; ++j){
      inner_step<false><<<grd2, blk2>>>(zbuf[(j-1)&1], zbuf[j&1], Xhp,
                                        ssbuf[(j-1)&1], ssbuf[j&1]);
    }
    final_div<<<grd2, blk2>>>(zbuf[0], Xp, ssbuf[0], (float4*)U);
  }
}

// round 10
// speedup vs baseline: 1.9240x; 1.0852x over previous
#include <cuda_runtime.h>
#include <cuda_fp16.h>
#include <cstdint>

#define H_ 512
#define W_ 512
#define C_ 64
#define WM_ 128
#define G8_ 8                       // half8 groups per pixel (C=64 -> 8 groups)
#define C4_ 16                      // float4 per pixel
#define HWG (H_*W_*G8_)             // uint4 elements per z component plane
#define HWC4 (H_*W_*C4_)
#define LMBDA 0.1f
#define INV_LMBDA 10.0f
#define TAU 0.1f

// ---------------- scratch (static device globals; no allocations) ----------
static __device__ uint4  g_zA[2*HWG];       // z ping (half): [comp][h][w][g]
static __device__ uint4  g_zB[2*HWG];       // z pong
static __device__ float4 g_X [HWC4];        // X = U - lambda*grad_f(U)   (fp32)
static __device__ float4 g_P [HWC4];        // P = lambda*(Y_H@B_t + R^T@Y_M)
static __device__ uint4  g_Xh[HWG];         // 10*X in half8 (stencil operand)
static __device__ uint4  g_Ph[HWG];         // 10*P in half8
static __device__ float  g_T [H_*WM_*C_];   // T[h] = R @ U[h]
static __device__ float  g_M1[C_*C_];       // M1 = B @ B_t
static __device__ float  g_Rt[W_*WM_];      // R^T
static __device__ float  g_ssA[4*H_];       // wide partials ping [chunk][comp][h]
static __device__ float  g_ssB[4*H_];       // wide partials pong

// ---------------- half8 (H8) utilities --------------------------------------
struct H8 { __half2 h[4]; };

__device__ __forceinline__ __half2 u2h(unsigned u){
  __half2 r; *reinterpret_cast<unsigned*>(&r) = u; return r;
}
__device__ __forceinline__ unsigned h2u(__half2 h){
  return *reinterpret_cast<unsigned*>(&h);
}
__device__ __forceinline__ H8 ld8h(const uint4* __restrict__ p, int idx){
  const uint4 v = p[idx];
  H8 r; r.h[0]=u2h(v.x); r.h[1]=u2h(v.y); r.h[2]=u2h(v.z); r.h[3]=u2h(v.w);
  return r;
}
__device__ __forceinline__ void st8h(uint4* __restrict__ p, int idx, const H8& r){
  p[idx] = make_uint4(h2u(r.h[0]), h2u(r.h[1]), h2u(r.h[2]), h2u(r.h[3]));
}
__device__ __forceinline__ H8 h8sub(H8 a, H8 b){ H8 r;
#pragma unroll
  for (int i=0;i<4;++i) r.h[i]=__hsub2(a.h[i],b.h[i]); return r; }
__device__ __forceinline__ H8 h8neg(H8 a){ H8 r;
#pragma unroll
  for (int i=0;i<4;++i) r.h[i]=__hneg2(a.h[i]); return r; }

// dz components (Chambolle adjoint), half arithmetic
__device__ __forceinline__ H8 dz1(const uint4* __restrict__ z1, int h, int w, int g){
  if (h == 0)     return ld8h(z1, w*G8_ + g);
  if (h == H_-1)  return h8neg(ld8h(z1, ((H_-2)*W_ + w)*G8_ + g));
  return h8sub(ld8h(z1, (h*W_ + w)*G8_ + g), ld8h(z1, ((h-1)*W_ + w)*G8_ + g));
}
__device__ __forceinline__ H8 dz2(const uint4* __restrict__ z2, int h, int w, int g){
  if (w == 0)     return ld8h(z2, (h*W_)*G8_ + g);
  if (w == W_-1)  return h8neg(ld8h(z2, (h*W_ + (W_-2))*G8_ + g));
  return h8sub(ld8h(z2, (h*W_ + w)*G8_ + g), ld8h(z2, (h*W_ + (w-1))*G8_ + g));
}

// d = s1*dz1 + s2*dz2 + Xh (Xh pre-scaled by 1/lambda)
__device__ __forceinline__ H8 dcalc(const uint4* __restrict__ z1,
                                    const uint4* __restrict__ z2,
                                    const uint4* __restrict__ Xh,
                                    int h, int w, int g, __half2 s1h, __half2 s2h){
  const H8 a = dz1(z1, h, w, g);
  const H8 b = dz2(z2, h, w, g);
  const H8 x = ld8h(Xh, (h*W_ + w)*G8_ + g);
  H8 d;
#pragma unroll
  for (int i=0;i<4;++i)
    d.h[i] = __hfma2(s1h, a.h[i], __hfma2(s2h, b.h[i], x.h[i]));
  return d;
}
// ONES variant: z == 1 -> dz terms are edge constants
__device__ __forceinline__ H8 dcalc1(const uint4* __restrict__ Xh, int h, int w, int g){
  const float a = (h==0)?1.f:((h==H_-1)?-1.f:0.f);
  const float b = (w==0)?1.f:((w==W_-1)?-1.f:0.f);
  const __half2 e = __float2half2_rn(a + b);
  const H8 x = ld8h(Xh, (h*W_ + w)*G8_ + g);
  H8 d;
#pragma unroll
  for (int i=0;i<4;++i) d.h[i] = __hadd2(x.h[i], e);
  return d;
}

// ---------------- fp32 helpers for final_div --------------------------------
struct F8 { float a[8]; };
__device__ __forceinline__ F8 h8f(const H8& x){
  F8 r;
#pragma unroll
  for (int i=0;i<4;++i){
    const float2 f = __half22float2(x.h[i]);
    r.a[2*i] = f.x; r.a[2*i+1] = f.y;
  }
  return r;
}

// ---------------- inline projection scale (wide partial layout) -------------
// ss layout: [0,H) c0/comp1, [H,2H) c0/comp2, [2H,3H) c1/comp1, [3H,4H) c1/comp2
__device__ __forceinline__ void get_scales(const float* __restrict__ ss,
                                           float& s1, float& s2){
  __shared__ float gs1[256], gs2[256];
  const int tid = threadIdx.x;
  float v1 = 0.f, v2 = 0.f;
  for (int h = tid; h < H_; h += 256){
    v1 += sqrtf(ss[h]       + ss[2*H_ + h]);
    v2 += sqrtf(ss[H_ + h]  + ss[3*H_ + h]);
  }
  gs1[tid] = v1; gs2[tid] = v2;
  __syncthreads();
  for (int s = 128; s > 0; s >>= 1){
    if (tid < s){ gs1[tid] += gs1[tid+s]; gs2[tid] += gs2[tid+s]; }
    __syncthreads();
  }
  const float n1 = gs1[0], n2 = gs2[0];
  s1 = (n1 > 1.f) ? (1.f/n1) : 1.f;
  s2 = (n2 > 1.f) ? (1.f/n2) : 1.f;
  __syncthreads();
}

// ---------------- fused dual iteration (all-half2 math) ---------------------
// grid (2, H), 256 threads; half-row (256 w) per CTA.
template<bool ONES>
__global__ __launch_bounds__(256)
void inner_step(const uint4* __restrict__ zin, uint4* __restrict__ zout,
                const uint4* __restrict__ Xh, const float* __restrict__ ssin,
                float* __restrict__ ssout)
{
  const int h   = blockIdx.y;
  const int w0  = blockIdx.x << 8;
  const int tid = threadIdx.x;
  const uint4* __restrict__ z1 = zin;
  const uint4* __restrict__ z2 = zin + HWG;
  float s1 = 1.f, s2 = 1.f;
  if (!ONES) get_scales(ssin, s1, s2);
  const __half2 s1h = __float2half2_rn(s1);
  const __half2 s2h = __float2half2_rn(s2);
  const __half2 tth = __float2half2_rn(2.f * TAU);
  const __half2 one = __float2half2_rn(1.f);
  float acc1 = 0.f, acc2 = 0.f;

#pragma unroll 1
  for (int p = 0; p < 8; ++p){
    const int flat = (p << 8) + tid;       // 0..2047
    const int w  = w0 + (flat >> 3);
    const int g  = flat & 7;
    const int idx = (h*W_ + w)*G8_ + g;

    H8 d00, z1c, z2c;
    if (ONES){
      d00 = dcalc1(Xh, h, w, g);
#pragma unroll
      for (int i=0;i<4;++i){ z1c.h[i] = one; z2c.h[i] = one; }
    } else {
      d00 = dcalc(z1, z2, Xh, h, w, g, s1h, s2h);
      const H8 za = ld8h(z1, idx), zb = ld8h(z2, idx);
#pragma unroll
      for (int i=0;i<4;++i){
        z1c.h[i] = __hmul2(s1h, za.h[i]);
        z2c.h[i] = __hmul2(s2h, zb.h[i]);
      }
    }

    H8 w1o = z1c, w2o = z2c;
    if (h < H_-1){
      const H8 dn = ONES ? dcalc1(Xh, h+1, w, g)
                         : dcalc(z1, z2, Xh, h+1, w, g, s1h, s2h);
#pragma unroll
      for (int i=0;i<4;++i)
        w1o.h[i] = __hfma2(tth, __hsub2(dn.h[i], d00.h[i]), z1c.h[i]);
    }
    if (w < W_-1){
      const H8 de = ONES ? dcalc1(Xh, h, w+1, g)
                         : dcalc(z1, z2, Xh, h, w+1, g, s1h, s2h);
#pragma unroll
      for (int i=0;i<4;++i)
        w2o.h[i] = __hfma2(tth, __hsub2(de.h[i], d00.h[i]), z2c.h[i]);
    }

    st8h(zout, idx, w1o);
    st8h(zout + HWG, idx, w2o);
#pragma unroll
    for (int i=0;i<4;++i){
      const float2 f1 = __half22float2(w1o.h[i]);
      const float2 f2 = __half22float2(w2o.h[i]);
      acc1 += f1.x*f1.x + f1.y*f1.y;
      acc2 += f2.x*f2.x + f2.y*f2.y;
    }
  }

  __shared__ float sm1[256], sm2[256];
  sm1[tid] = acc1; sm2[tid] = acc2;
  __syncthreads();
  for (int s = 128; s > 0; s >>= 1){
    if (tid < s){ sm1[tid] += sm1[tid+s]; sm2[tid] += sm2[tid+s]; }
    __syncthreads();
  }
  if (tid == 0){
    const int base = blockIdx.x ? 2*H_ : 0;   // disjoint slots per chunk
    ssout[base + h]       = sm1[0];
    ssout[base + H_ + h]  = sm2[0];
  }
}

// proxg output: U = X + LMBDA * div(s .* z)   (fp32 base, fp32 epilogue)
__global__ __launch_bounds__(256)
void final_div(const uint4* __restrict__ zin, const float4* __restrict__ Xp,
               const float* __restrict__ ssin, float4* __restrict__ U)
{
  const int h   = blockIdx.y;
  const int w0  = blockIdx.x << 8;
  const int tid = threadIdx.x;
  const uint4* __restrict__ z1 = zin;
  const uint4* __restrict__ z2 = zin + HWG;
  float s1, s2;
  get_scales(ssin, s1, s2);
#pragma unroll 1
  for (int p = 0; p < 8; ++p){
    const int flat = (p << 8) + tid;
    const int w  = w0 + (flat >> 3);
    const int g  = flat & 7;
    const F8 a = h8f(dz1(z1, h, w, g));
    const F8 b = h8f(dz2(z2, h, w, g));
    const int i4 = (h*W_ + w)*C4_ + 2*g;
    const float4 xp = Xp[i4], xq = Xp[i4+1];
    const float xv[8] = {xp.x,xp.y,xp.z,xp.w, xq.x,xq.y,xq.z,xq.w};
    float r[8];
#pragma unroll
    for (int i = 0; i < 8; ++i)
      r[i] = fmaf(LMBDA, fmaf(s1, a.a[i], s2*b.a[i]), xv[i]);
    U[i4]   = make_float4(r[0], r[1], r[2], r[3]);
    U[i4+1] = make_float4(r[4], r[5], r[6], r[7]);
  }
}

// ---------------- fp16 tensor-core GEMM (2-term hi/lo split) -----------------
// fp16 hi has an 11-bit effective mantissa == tf32; 2-term ah*(bh+bl) keeps the
// same error structure as the previous tf32 2-term path, at half the issue work.
__device__ __forceinline__ void mma_f16(float (&c)[4], const uint32_t* a,
                                        const uint32_t* b){
  asm volatile(
    "mma.sync.aligned.m16n8k16.row.col.f32.f16.f16.f32 "
    "{%0,%1,%2,%3}, {%4,%5,%6,%7}, {%8,%9}, {%0,%1,%2,%3};"
    : "+f"(c[0]), "+f"(c[1]), "+f"(c[2]), "+f"(c[3])
    : "r"(a[0]), "r"(a[1]), "r"(a[2]), "r"(a[3]), "r"(b[0]), "r"(b[1]));
}

#define SAH 20                     // A smem stride (b32 units; 16 used + 4 pad)
#define SBH 20                     // B smem stride
#define SMEM_TC ((128*SAH + 64*SBH*2)*4)   // 20.5 KB

// out[h][m0:m0+128, 0:64] = cU*Uin + cMM*( [do_p1] Uin@N1  +  A2@Bin[h] ) + cP*Pb
// If outh != nullptr, also writes INV_LMBDA*result to the half8 buffer.
__global__ __launch_bounds__(256)
void gemm_tc(float* __restrict__ out, int out_h, __half* __restrict__ outh,
             const float* __restrict__ Uin,
             const float* __restrict__ N1,
             const float* __restrict__ A2,
             const float* __restrict__ Bin, int bin_h,
             const float* __restrict__ Pb,
             int K2, int do_p1, float cU, float cMM, float cP)
{
  extern __shared__ unsigned smemU[];
  unsigned* Ah = smemU;             // [128][SAH]  A hi, packed half2 (k pairs)
  unsigned* Bh = Ah + 128*SAH;      // [64][SBH]   B hi, transposed packed
  unsigned* Bl = Bh + 64*SBH;       // [64][SBH]   B lo

  const int h   = blockIdx.y;
  const int m0  = blockIdx.x << 7;
  const int tid = threadIdx.x;
  const int lane = tid & 31, wid = tid >> 5;
  const int wm = wid & 3, wn = wid >> 2;      // 4 x 2 warps over (128m, 64n)
  const int gid = lane >> 2, t4 = lane & 3;

  float acc[2][4][4];
#pragma unroll
  for (int i = 0; i < 2; ++i)
#pragma unroll
    for (int j = 0; j < 4; ++j)
#pragma unroll
      for (int q = 0; q < 4; ++q) acc[i][j][q] = 0.f;

  for (int ph = 0; ph < 2; ++ph){
    const float* Ag; int lda; const float* Bg; int Kp;
    if (ph == 0){
      if (!do_p1) continue;
      Ag = Uin + (size_t)h*32768 + (size_t)m0*64; lda = 64; Bg = N1; Kp = 64;
    } else {
      Ag = A2 + (size_t)m0*K2; lda = K2; Bg = Bin + (size_t)h*bin_h; Kp = K2;
    }
    for (int k0 = 0; k0 < Kp; k0 += 32){
      __syncthreads();
      // fill A chunk 128x32: hi only, packed half2 by k-pairs
      {
        const int row0 = tid >> 3;            // 0..31
        const int k4   = (tid & 7) << 2;      // 0,4,..,28
#pragma unroll
        for (int r = 0; r < 4; ++r){
          const int row = row0 + 32*r;
          const float4 v = *(const float4*)(Ag + (size_t)row*lda + k0 + k4);
          Ah[row*SAH + (k4>>1)]     = h2u(__floats2half2_rn(v.x, v.y));
          Ah[row*SAH + (k4>>1) + 1] = h2u(__floats2half2_rn(v.z, v.w));
        }
      }
      // fill B chunk 32x64: transpose to [n][k2], hi/lo split, packed half2
      {
        const int k2 = tid & 15;              // k-pair index 0..15
        const int n4 = (tid >> 4) << 2;       // 0,4,..,60
        const float* B0 = Bg + (size_t)(k0 + 2*k2)*64 + n4;
        const float4 va = *(const float4*)B0;        // k even row
        const float4 vb = *(const float4*)(B0 + 64); // k odd row
        const float av[4] = {va.x, va.y, va.z, va.w};
        const float bv[4] = {vb.x, vb.y, vb.z, vb.w};
#pragma unroll
        for (int j = 0; j < 4; ++j){
          const __half ha = __float2half_rn(av[j]);
          const __half hb = __float2half_rn(bv[j]);
          const __half la = __float2half_rn(av[j] - __half2float(ha));
          const __half lb = __float2half_rn(bv[j] - __half2float(hb));
          Bh[(n4+j)*SBH + k2] = h2u(__halves2half2(ha, hb));
          Bl[(n4+j)*SBH + k2] = h2u(__halves2half2(la, lb));
        }
      }
      __syncthreads();
#pragma unroll
      for (int kf = 0; kf < 2; ++kf){         // two k16 fragments per chunk
        const int base = kf*8;
        uint32_t ah[2][4];
#pragma unroll
        for (int fm = 0; fm < 2; ++fm){
          const int r0 = wm*32 + fm*16 + gid;
          ah[fm][0] = Ah[r0*SAH + base + t4];
          ah[fm][1] = Ah[(r0+8)*SAH + base + t4];
          ah[fm][2] = Ah[r0*SAH + base + t4 + 4];
          ah[fm][3] = Ah[(r0+8)*SAH + base + t4 + 4];
        }
        uint32_t bhv[4][2], blv[4][2];
#pragma unroll
        for (int fn = 0; fn < 4; ++fn){
          const int n = wn*32 + fn*8 + gid;
          bhv[fn][0] = Bh[n*SBH + base + t4];
          bhv[fn][1] = Bh[n*SBH + base + t4 + 4];
          blv[fn][0] = Bl[n*SBH + base + t4];
          blv[fn][1] = Bl[n*SBH + base + t4 + 4];
        }
#pragma unroll
        for (int fm = 0; fm < 2; ++fm)
#pragma unroll
          for (int fn = 0; fn < 4; ++fn){
            mma_f16(acc[fm][fn], ah[fm], bhv[fn]);   // hi*hi
            mma_f16(acc[fm][fn], ah[fm], blv[fn]);   // hi*lo
          }
      }
    }
  }

  // epilogue (same C frag layout as m16n8k8)
  float* Oh = out + (size_t)h*out_h;
  __half* Ohh = outh ? (outh + (size_t)h*out_h) : nullptr;
  const float* Uh = Uin + (size_t)h*32768;
  const float* Ph = Pb  + (size_t)h*32768;
#pragma unroll
  for (int fm = 0; fm < 2; ++fm){
#pragma unroll
    for (int fn = 0; fn < 4; ++fn){
      const int r0 = m0 + wm*32 + fm*16 + gid;
      const int c0 = wn*32 + fn*8 + 2*t4;
#pragma unroll
      for (int half = 0; half < 2; ++half){
        const int r = r0 + 8*half;
        float v0 = cMM * acc[fm][fn][2*half];
        float v1 = cMM * acc[fm][fn][2*half + 1];
        if (cU != 0.f){
          const float2 u = *(const float2*)(Uh + (size_t)r*64 + c0);
          v0 += cU*u.x; v1 += cU*u.y;
        }
        if (cP != 0.f){
          const float2 pv = *(const float2*)(Ph + (size_t)r*64 + c0);
          v0 += cP*pv.x; v1 += cP*pv.y;
        }
        *(float2*)(Oh + (size_t)r*64 + c0) = make_float2(v0, v1);
        if (Ohh)
          *reinterpret_cast<__half2*>(Ohh + (size_t)r*64 + c0) =
            __floats2half2_rn(INV_LMBDA*v0, INV_LMBDA*v1);
      }
    }
  }
}

__global__ void transpose_R(float* __restrict__ Rt, const float* __restrict__ R)
{
  const int i = blockIdx.x*256 + threadIdx.x;
  if (i < W_*WM_){
    const int w = i / WM_, m = i % WM_;
    Rt[i] = R[m*W_ + w];
  }
}

__global__ void compute_M1(float* __restrict__ M1, const float* __restrict__ B,
                           const float* __restrict__ Bt)
{
  const int i = blockIdx.x*256 + threadIdx.x;
  if (i < C_*C_){
    const int m = i >> 6, n = i & 63;
    float s = 0.f;
#pragma unroll 8
    for (int k = 0; k < C_; ++k) s += B[m*C_ + k]*Bt[k*C_ + n];
    M1[i] = s;
  }
}

// ---------------- driver ----------------------------------------------------
extern "C" void kernel_launch(void* const* d_in, const int* in_sizes, int n_in,
                              void* d_out, int out_size)
{
  const float* Y_H = (const float*)d_in[0];
  const float* Y_M = (const float*)d_in[1];
  const float* B   = (const float*)d_in[2];
  const float* B_t = (const float*)d_in[3];
  const float* R   = (const float*)d_in[4];
  float* U = (float*)d_out;

  uint4 *zA, *zB, *Xh, *Ph;
  float4 *X, *P;
  float *T, *M1, *Rt, *ssA, *ssB;
  cudaGetSymbolAddress((void**)&zA,  g_zA);
  cudaGetSymbolAddress((void**)&zB,  g_zB);
  cudaGetSymbolAddress((void**)&X,   g_X);
  cudaGetSymbolAddress((void**)&P,   g_P);
  cudaGetSymbolAddress((void**)&Xh,  g_Xh);
  cudaGetSymbolAddress((void**)&Ph,  g_Ph);
  cudaGetSymbolAddress((void**)&T,   g_T);
  cudaGetSymbolAddress((void**)&M1,  g_M1);
  cudaGetSymbolAddress((void**)&Rt,  g_Rt);
  cudaGetSymbolAddress((void**)&ssA, g_ssA);
  cudaGetSymbolAddress((void**)&ssB, g_ssB);

  const dim3 blk2(256);
  const dim3 grd2(2, H_);

  transpose_R<<<(W_*WM_ + 255)/256, 256>>>(Rt, R);
  compute_M1 <<<(C_*C_ + 255)/256, 256>>>(M1, B, B_t);
  // P = LMBDA*(Y_H@B_t + Rt@Y_M), plus Ph = 10*P in half
  gemm_tc<<<dim3(4, H_), 256, SMEM_TC>>>((float*)P, 32768, (__half*)Ph,
                                         Y_H, B_t, Rt, Y_M, WM_*C_,
                                         (const float*)P,
                                         WM_, 1, 0.f, LMBDA, 0.f);

  uint4* zbuf[2]  = { zA, zB };
  float* ssbuf[2] = { ssA, ssB };
  for (int it = 0; it < 5; ++it){
    const uint4* Xhp;
    const float4* Xp;
    if (it == 0){
      Xhp = Ph; Xp = P;                         // U = 0 -> X = P exactly
    } else {
      // T[h] = R @ U[h]
      gemm_tc<<<dim3(1, H_), 256, SMEM_TC>>>(T, WM_*C_, (__half*)nullptr,
                                             U, M1, R, U, W_*C_,
                                             (const float*)P,
                                             W_, 0, 0.f, 1.f, 0.f);
      // X = U - LMBDA*(U@M1 + Rt@T) + P, plus Xh = 10*X in half
      gemm_tc<<<dim3(4, H_), 256, SMEM_TC>>>((float*)X, 32768, (__half*)Xh,
                                             U, M1, Rt, T, WM_*C_,
                                             (const float*)P,
                                             WM_, 1, 1.f, -LMBDA, 1.f);
      Xhp = Xh; Xp = X;
    }
    inner_step<true><<<grd2, blk2>>>(zbuf[1], zbuf[0], Xhp, ssbuf[1], ssbuf[0]);
    for (int j = 1; j < 5; ++j){
      inner_step<false><<<grd2, blk2>>>(zbuf[(j-1)&1], zbuf[j&1], Xhp,
                                        ssbuf[(j-1)&1], ssbuf[j&1]);
    }
    final_div<<<grd2, blk2>>>(zbuf[0], Xp, ssbuf[0], (float4*)U);
  }
}